// round 1
// baseline (speedup 1.0000x reference)
#include <cuda_runtime.h>
#include <math.h>

#define SEQ   1024
#define BSZ   8
#define EMB   512
#define NHEAD 8
#define HDIM  64
#define NROWS (SEQ*BSZ)      // 8192
#define NBH   (BSZ*NHEAD)    // 64
#define FLTMAX 3.402823466e38f
#define T1C 0.6f
#define T2C 0.4f

// ---------------- scratch (device globals; no allocation allowed) -------------
__device__ float g_qs [NROWS*EMB];   // sem  q proj   [t*8+b][e]
__device__ float g_ks [NROWS*EMB];   // sem  k proj
__device__ float g_qc [NROWS*EMB];   // cont q proj
__device__ float g_kc [NROWS*EMB];   // cont k proj
__device__ float g_v  [NROWS*EMB];   // v proj
__device__ float g_qsT[NBH*HDIM*SEQ];// [bh][d][t], pre-scaled by 1/8
__device__ float g_ksT[NBH*HDIM*SEQ];
__device__ float g_qcT[NBH*HDIM*SEQ];// pre-scaled by 1/8
__device__ float g_kcT[NBH*HDIM*SEQ];
__device__ float g_o  [NROWS*EMB];   // T1*o_sca + T2*o_ssa (pre out-proj)

// ---------------- fp32 GEMM: C[M,512] = X[M,512] @ W[512,512]^T + bias*bs ------
__global__ __launch_bounds__(256)
void gemm_bias(const float* __restrict__ X, const float* __restrict__ W,
               const float* __restrict__ bias, float* __restrict__ C, float bscale) {
    __shared__ float As[16][68];
    __shared__ float Bs[16][68];
    const int bm = blockIdx.y << 6;
    const int bn = blockIdx.x << 6;
    const int tid = threadIdx.x;
    const int tx = tid & 15, ty = tid >> 4;
    const int lr = tid >> 2, lk = (tid & 3) << 2;

    float acc[4][4];
#pragma unroll
    for (int i = 0; i < 4; i++)
#pragma unroll
        for (int j = 0; j < 4; j++) acc[i][j] = 0.f;

    const float* xp = X + (size_t)(bm + lr) * EMB + lk;
    const float* wp = W + (size_t)(bn + lr) * EMB + lk;

    for (int k0 = 0; k0 < EMB; k0 += 16) {
        float4 xa = *(const float4*)(xp + k0);
        float4 wb = *(const float4*)(wp + k0);
        __syncthreads();
        As[lk+0][lr] = xa.x; As[lk+1][lr] = xa.y; As[lk+2][lr] = xa.z; As[lk+3][lr] = xa.w;
        Bs[lk+0][lr] = wb.x; Bs[lk+1][lr] = wb.y; Bs[lk+2][lr] = wb.z; Bs[lk+3][lr] = wb.w;
        __syncthreads();
#pragma unroll
        for (int k = 0; k < 16; k++) {
            float4 a  = *(const float4*)&As[k][ty << 2];
            float4 bv = *(const float4*)&Bs[k][tx << 2];
            float av[4] = {a.x, a.y, a.z, a.w};
            float bb[4] = {bv.x, bv.y, bv.z, bv.w};
#pragma unroll
            for (int i = 0; i < 4; i++)
#pragma unroll
                for (int j = 0; j < 4; j++) acc[i][j] = fmaf(av[i], bb[j], acc[i][j]);
        }
    }
#pragma unroll
    for (int i = 0; i < 4; i++) {
        float4 o;
        o.x = acc[i][0] + bias[bn + (tx<<2) + 0] * bscale;
        o.y = acc[i][1] + bias[bn + (tx<<2) + 1] * bscale;
        o.z = acc[i][2] + bias[bn + (tx<<2) + 2] * bscale;
        o.w = acc[i][3] + bias[bn + (tx<<2) + 3] * bscale;
        *(float4*)&C[(size_t)(bm + (ty<<2) + i) * EMB + bn + (tx<<2)] = o;
    }
}

// ------- head transpose: out[bh][d][t] = in[t][b][h*64+d] * scale --------------
__global__ __launch_bounds__(256)
void transpose_head(const float* __restrict__ in, float* __restrict__ out, float scale) {
    __shared__ float tile[32][33];
    const int bh = blockIdx.z, b = bh >> 3, h = bh & 7;
    const int t0 = blockIdx.x << 5;
    const int d0 = blockIdx.y << 5;
    const int tx = threadIdx.x, ty = threadIdx.y;   // 32 x 8
#pragma unroll
    for (int i = 0; i < 32; i += 8)
        tile[ty + i][tx] = in[(size_t)(t0 + ty + i) * (BSZ*EMB) + b * EMB + h * HDIM + d0 + tx] * scale;
    __syncthreads();
#pragma unroll
    for (int i = 0; i < 32; i += 8)
        out[(size_t)(bh * HDIM + d0 + ty + i) * SEQ + t0 + tx] = tile[tx][ty + i];
}

// ---------------- fused dual-path attention -----------------------------------
// grid: (SEQ/32, 64).  256 threads.
// threads 0..63   : sem-path scores (4q x 4s tiles) + online softmax
// threads 64..127 : content-path scores + running argmax
// all 256         : PV accumulation (qr = tid>>3, dims dg*8..dg*8+7)
__global__ __launch_bounds__(256)
void attn_kernel(const float* __restrict__ sem_map, float* __restrict__ Ocomb) {
    __shared__ float qT[2][64][32];
    __shared__ float kT[2][64][32];
    __shared__ float vt[32][64];
    __shared__ float wt[32][32];
    __shared__ float s_fac[32];
    __shared__ float s_l[32];
    __shared__ int   s_bidx[32];

    const int bh = blockIdx.y, b = bh >> 3, h = bh & 7;
    const int q0 = blockIdx.x << 5;
    const int tid = threadIdx.x;

    // load q tiles (both paths), transposed layout, q already pre-scaled by 1/8
    for (int i = tid; i < 512; i += 256) {
        int d = i >> 3, g4 = (i & 7) << 2;
        *(float4*)&qT[0][d][g4] = *(const float4*)&g_qsT[(size_t)(bh*HDIM + d)*SEQ + q0 + g4];
        *(float4*)&qT[1][d][g4] = *(const float4*)&g_qcT[(size_t)(bh*HDIM + d)*SEQ + q0 + g4];
    }

    const bool isScore = (tid < 128);
    const int p  = tid >> 6;          // 0 = sem, 1 = content (when isScore)
    const int rg = (tid & 63) >> 3;   // row group (4 rows)
    const int cg = tid & 7;           // col group (4 cols)

    float mrun[4], lrun[4], bsc[4];
    int   bix[4];
#pragma unroll
    for (int i = 0; i < 4; i++) { mrun[i] = -FLTMAX; lrun[i] = 0.f; bsc[i] = -FLTMAX; bix[i] = 0; }

    const int qr = tid >> 3;          // PV row
    const int dg = (tid & 7) << 3;    // PV dim base
    float acc[8];
#pragma unroll
    for (int i = 0; i < 8; i++) acc[i] = 0.f;

    for (int s0 = 0; s0 < SEQ; s0 += 32) {
        __syncthreads();   // previous PV finished before we overwrite k/v/wt
        for (int i = tid; i < 512; i += 256) {
            int d = i >> 3, g4 = (i & 7) << 2;
            *(float4*)&kT[0][d][g4] = *(const float4*)&g_ksT[(size_t)(bh*HDIM + d)*SEQ + s0 + g4];
            *(float4*)&kT[1][d][g4] = *(const float4*)&g_kcT[(size_t)(bh*HDIM + d)*SEQ + s0 + g4];
            int r = i >> 4, d4 = (i & 15) << 2;
            *(float4*)&vt[r][d4]    = *(const float4*)&g_v[(size_t)((s0 + r)*BSZ + b)*EMB + h*HDIM + d4];
        }
        __syncthreads();

        if (isScore) {
            float sc[4][4];
#pragma unroll
            for (int i = 0; i < 4; i++)
#pragma unroll
                for (int j = 0; j < 4; j++) sc[i][j] = 0.f;
#pragma unroll 16
            for (int d = 0; d < 64; d++) {
                float4 a  = *(const float4*)&qT[p][d][rg << 2];
                float4 bv = *(const float4*)&kT[p][d][cg << 2];
                float av[4] = {a.x, a.y, a.z, a.w};
                float bb[4] = {bv.x, bv.y, bv.z, bv.w};
#pragma unroll
                for (int i = 0; i < 4; i++)
#pragma unroll
                    for (int j = 0; j < 4; j++) sc[i][j] = fmaf(av[i], bb[j], sc[i][j]);
            }
            // mask: sem_map[t][s] < 0.5 -> -FLT_MAX (both paths)
#pragma unroll
            for (int i = 0; i < 4; i++) {
                float4 mk = *(const float4*)&sem_map[(size_t)(q0 + (rg<<2) + i)*SEQ + s0 + (cg<<2)];
                if (mk.x < 0.5f) sc[i][0] = -FLTMAX;
                if (mk.y < 0.5f) sc[i][1] = -FLTMAX;
                if (mk.z < 0.5f) sc[i][2] = -FLTMAX;
                if (mk.w < 0.5f) sc[i][3] = -FLTMAX;
            }
            if (p == 0) {  // SCA: online softmax
#pragma unroll
                for (int i = 0; i < 4; i++) {
                    float tm = fmaxf(fmaxf(sc[i][0], sc[i][1]), fmaxf(sc[i][2], sc[i][3]));
#pragma unroll
                    for (int off = 1; off < 8; off <<= 1)
                        tm = fmaxf(tm, __shfl_xor_sync(0xffffffffu, tm, off, 8));
                    float mnew = fmaxf(mrun[i], tm);
                    float fac  = expf(mrun[i] - mnew);
                    float w0 = expf(sc[i][0] - mnew);
                    float w1 = expf(sc[i][1] - mnew);
                    float w2 = expf(sc[i][2] - mnew);
                    float w3 = expf(sc[i][3] - mnew);
                    float sum = (w0 + w1) + (w2 + w3);
#pragma unroll
                    for (int off = 1; off < 8; off <<= 1)
                        sum += __shfl_xor_sync(0xffffffffu, sum, off, 8);
                    lrun[i] = lrun[i] * fac + sum;
                    mrun[i] = mnew;
                    if (cg == 0) s_fac[(rg<<2) + i] = fac;
                    *(float4*)&wt[(rg<<2) + i][cg<<2] = make_float4(w0, w1, w2, w3);
                }
            } else {       // SSA: running argmax (first max wins)
#pragma unroll
                for (int i = 0; i < 4; i++)
#pragma unroll
                    for (int j = 0; j < 4; j++) {
                        float v = sc[i][j];
                        if (v > bsc[i]) { bsc[i] = v; bix[i] = s0 + (cg<<2) + j; }
                    }
            }
        }
        __syncthreads();

        // PV: all 256 threads
        {
            float fac = s_fac[qr];
#pragma unroll
            for (int i = 0; i < 8; i++) acc[i] *= fac;
#pragma unroll 4
            for (int s = 0; s < 32; s++) {
                float w  = wt[qr][s];
                float4 v0 = *(const float4*)&vt[s][dg];
                float4 v1 = *(const float4*)&vt[s][dg + 4];
                acc[0] = fmaf(w, v0.x, acc[0]); acc[1] = fmaf(w, v0.y, acc[1]);
                acc[2] = fmaf(w, v0.z, acc[2]); acc[3] = fmaf(w, v0.w, acc[3]);
                acc[4] = fmaf(w, v1.x, acc[4]); acc[5] = fmaf(w, v1.y, acc[5]);
                acc[6] = fmaf(w, v1.z, acc[6]); acc[7] = fmaf(w, v1.w, acc[7]);
            }
        }
    }

    // finalize row stats
    if (isScore) {
        if (p == 0) {
            if (cg == 0) {
#pragma unroll
                for (int i = 0; i < 4; i++) s_l[(rg<<2) + i] = lrun[i];
            }
        } else {
#pragma unroll
            for (int i = 0; i < 4; i++) {
                float bs = bsc[i]; int bi = bix[i];
#pragma unroll
                for (int off = 1; off < 8; off <<= 1) {
                    float os = __shfl_xor_sync(0xffffffffu, bs, off, 8);
                    int   oi = __shfl_xor_sync(0xffffffffu, bi, off, 8);
                    if (os > bs || (os == bs && oi < bi)) { bs = os; bi = oi; }
                }
                if (cg == 0) s_bidx[(rg<<2) + i] = bi;
            }
        }
    }
    __syncthreads();

    // combine: T1 * (acc/l) + T2 * v[argmax]
    {
        float rl = 1.0f / s_l[qr];
        int   bi = s_bidx[qr];
        const float* vp = &g_v[(size_t)(bi*BSZ + b)*EMB + h*HDIM + dg];
        float4 va = *(const float4*)(vp);
        float4 vb = *(const float4*)(vp + 4);
        float4 o0, o1;
        o0.x = T1C*acc[0]*rl + T2C*va.x;  o0.y = T1C*acc[1]*rl + T2C*va.y;
        o0.z = T1C*acc[2]*rl + T2C*va.z;  o0.w = T1C*acc[3]*rl + T2C*va.w;
        o1.x = T1C*acc[4]*rl + T2C*vb.x;  o1.y = T1C*acc[5]*rl + T2C*vb.y;
        o1.z = T1C*acc[6]*rl + T2C*vb.z;  o1.w = T1C*acc[7]*rl + T2C*vb.w;
        float* op = &Ocomb[(size_t)((q0 + qr)*BSZ + b)*EMB + h*HDIM + dg];
        *(float4*)(op)     = o0;
        *(float4*)(op + 4) = o1;
    }
}

// -------------------------------------------------------------------------------
extern "C" void kernel_launch(void* const* d_in, const int* in_sizes, int n_in,
                              void* d_out, int out_size) {
    const float* query = (const float*)d_in[0];
    const float* key   = (const float*)d_in[1];
    const float* value = (const float*)d_in[2];
    const float* qsem  = (const float*)d_in[3];
    const float* ksem  = (const float*)d_in[4];
    const float* smap  = (const float*)d_in[5];
    const float* Wi    = (const float*)d_in[6];
    const float* bi    = (const float*)d_in[7];
    const float* Wo    = (const float*)d_in[8];
    const float* bo    = (const float*)d_in[9];
    float* out = (float*)d_out;

    float *p_qs, *p_ks, *p_qc, *p_kc, *p_v, *p_qsT, *p_ksT, *p_qcT, *p_kcT, *p_o;
    cudaGetSymbolAddress((void**)&p_qs,  g_qs);
    cudaGetSymbolAddress((void**)&p_ks,  g_ks);
    cudaGetSymbolAddress((void**)&p_qc,  g_qc);
    cudaGetSymbolAddress((void**)&p_kc,  g_kc);
    cudaGetSymbolAddress((void**)&p_v,   g_v);
    cudaGetSymbolAddress((void**)&p_qsT, g_qsT);
    cudaGetSymbolAddress((void**)&p_ksT, g_ksT);
    cudaGetSymbolAddress((void**)&p_qcT, g_qcT);
    cudaGetSymbolAddress((void**)&p_kcT, g_kcT);
    cudaGetSymbolAddress((void**)&p_o,   g_o);

    dim3 ggrid(EMB/64, NROWS/64);
    // 5 in-projections (Wq rows 0..511, Wk 512..1023, Wv 1024..1535)
    gemm_bias<<<ggrid, 256>>>(qsem,  Wi,               bi,        p_qs, 1.0f);
    gemm_bias<<<ggrid, 256>>>(ksem,  Wi + 512*EMB,     bi + 512,  p_ks, 1.0f);
    gemm_bias<<<ggrid, 256>>>(query, Wi,               bi,        p_qc, 1.0f);
    gemm_bias<<<ggrid, 256>>>(key,   Wi + 512*EMB,     bi + 512,  p_kc, 1.0f);
    gemm_bias<<<ggrid, 256>>>(value, Wi + 1024*EMB,    bi + 1024, p_v,  1.0f);

    dim3 tgrid(SEQ/32, HDIM/32, NBH), tblk(32, 8);
    transpose_head<<<tgrid, tblk>>>(p_qs, p_qsT, 0.125f);  // q pre-scaled by 1/sqrt(64)
    transpose_head<<<tgrid, tblk>>>(p_ks, p_ksT, 1.0f);
    transpose_head<<<tgrid, tblk>>>(p_qc, p_qcT, 0.125f);
    transpose_head<<<tgrid, tblk>>>(p_kc, p_kcT, 1.0f);

    attn_kernel<<<dim3(SEQ/32, NBH), 256>>>(smap, p_o);

    gemm_bias<<<ggrid, 256>>>(p_o, Wo, bo, out, T1C + T2C);  // bias scaled by (T1+T2)
}

// round 2
// speedup vs baseline: 1.3360x; 1.3360x over previous
#include <cuda_runtime.h>
#include <math.h>

#define SEQ   1024
#define BSZ   8
#define EMB   512
#define NHEAD 8
#define HDIM  64
#define NROWS (SEQ*BSZ)      // 8192
#define NBH   (BSZ*NHEAD)    // 64
#define FLTMAX 3.402823466e38f
#define T1C 0.6f
#define T2C 0.4f

// ---------------- scratch (device globals; no allocation allowed) -------------
__device__ float g_qs [NROWS*EMB];
__device__ float g_ks [NROWS*EMB];
__device__ float g_qc [NROWS*EMB];
__device__ float g_kc [NROWS*EMB];
__device__ float g_v  [NROWS*EMB];
__device__ float g_qsT[NBH*HDIM*SEQ];   // [bh][d][t], q pre-scaled by 1/8
__device__ float g_ksT[NBH*HDIM*SEQ];
__device__ float g_qcT[NBH*HDIM*SEQ];
__device__ float g_kcT[NBH*HDIM*SEQ];
__device__ float g_o  [NROWS*EMB];

// ---------------- fp32 GEMM: C[M,512] = X[M,512] @ W[512,512]^T + bias*bs ------
__global__ __launch_bounds__(256)
void gemm_bias(const float* __restrict__ X, const float* __restrict__ W,
               const float* __restrict__ bias, float* __restrict__ C, float bscale) {
    __shared__ float As[16][68];
    __shared__ float Bs[16][68];
    const int bm = blockIdx.y << 6;
    const int bn = blockIdx.x << 6;
    const int tid = threadIdx.x;
    const int tx = tid & 15, ty = tid >> 4;
    const int lr = tid >> 2, lk = (tid & 3) << 2;

    float acc[4][4];
#pragma unroll
    for (int i = 0; i < 4; i++)
#pragma unroll
        for (int j = 0; j < 4; j++) acc[i][j] = 0.f;

    const float* xp = X + (size_t)(bm + lr) * EMB + lk;
    const float* wp = W + (size_t)(bn + lr) * EMB + lk;

    for (int k0 = 0; k0 < EMB; k0 += 16) {
        float4 xa = *(const float4*)(xp + k0);
        float4 wb = *(const float4*)(wp + k0);
        __syncthreads();
        As[lk+0][lr] = xa.x; As[lk+1][lr] = xa.y; As[lk+2][lr] = xa.z; As[lk+3][lr] = xa.w;
        Bs[lk+0][lr] = wb.x; Bs[lk+1][lr] = wb.y; Bs[lk+2][lr] = wb.z; Bs[lk+3][lr] = wb.w;
        __syncthreads();
#pragma unroll
        for (int k = 0; k < 16; k++) {
            float4 a  = *(const float4*)&As[k][ty << 2];
            float4 bv = *(const float4*)&Bs[k][tx << 2];
            float av[4] = {a.x, a.y, a.z, a.w};
            float bb[4] = {bv.x, bv.y, bv.z, bv.w};
#pragma unroll
            for (int i = 0; i < 4; i++)
#pragma unroll
                for (int j = 0; j < 4; j++) acc[i][j] = fmaf(av[i], bb[j], acc[i][j]);
        }
    }
#pragma unroll
    for (int i = 0; i < 4; i++) {
        float4 o;
        o.x = acc[i][0] + bias[bn + (tx<<2) + 0] * bscale;
        o.y = acc[i][1] + bias[bn + (tx<<2) + 1] * bscale;
        o.z = acc[i][2] + bias[bn + (tx<<2) + 2] * bscale;
        o.w = acc[i][3] + bias[bn + (tx<<2) + 3] * bscale;
        *(float4*)&C[(size_t)(bm + (ty<<2) + i) * EMB + bn + (tx<<2)] = o;
    }
}

// ------- head transpose: out[bh][d][t] = in[t][b][h*64+d] * scale --------------
__global__ __launch_bounds__(256)
void transpose_head(const float* __restrict__ in, float* __restrict__ out, float scale) {
    __shared__ float tile[32][33];
    const int bh = blockIdx.z, b = bh >> 3, h = bh & 7;
    const int t0 = blockIdx.x << 5;
    const int d0 = blockIdx.y << 5;
    const int tx = threadIdx.x, ty = threadIdx.y;   // 32 x 8
#pragma unroll
    for (int i = 0; i < 32; i += 8)
        tile[ty + i][tx] = in[(size_t)(t0 + ty + i) * (BSZ*EMB) + b * EMB + h * HDIM + d0 + tx] * scale;
    __syncthreads();
#pragma unroll
    for (int i = 0; i < 32; i += 8)
        out[(size_t)(bh * HDIM + d0 + ty + i) * SEQ + t0 + tx] = tile[tx][ty + i];
}

// ---------------- fused dual-path attention (64q x 64s tiles) ------------------
// 256 threads.  Score phase: all threads. tid<128 -> sem path, tid>=128 -> content.
//   micro-tile 4q x 8s: rg = (tid&127)>>3 (16 groups), cg = tid&7 (8 groups)
// PV phase: all threads, micro-tile 4q x 4d: qg = tid>>4, dg = tid&15
// smem (dynamic):
//   qT [2][64][64]  kT [2][64][64]   (outer-product layout [path][d][row])
//   vt [64][68]     wt [64][68]      (wt = softmax weights [q][s])
//   sfac[64] sl[64] sbix[64]
#define SM_QT   0
#define SM_KT   8192
#define SM_VT   16384
#define SM_WT   (16384 + 64*68)
#define SM_FAC  (16384 + 2*64*68)
#define SM_L    (SM_FAC + 64)
#define SM_BIX  (SM_L + 64)
#define SM_FLOATS (SM_BIX + 64)

__global__ __launch_bounds__(256, 2)
void attn_kernel(const float* __restrict__ sem_map, float* __restrict__ Ocomb) {
    extern __shared__ float sm[];
    float* qTs  = sm + SM_QT;
    float* kTs  = sm + SM_KT;
    float* vts  = sm + SM_VT;
    float* wts  = sm + SM_WT;
    float* sfac = sm + SM_FAC;
    float* sl   = sm + SM_L;
    int*   sbix = (int*)(sm + SM_BIX);

    const int bh = blockIdx.y, b = bh >> 3, h = bh & 7;
    const int q0 = blockIdx.x << 6;
    const int tid = threadIdx.x;

    // q tiles (both paths), layout [p][d][q]
    for (int i = tid; i < 2048; i += 256) {
        int p = i >> 10, rem = i & 1023;
        int d = rem >> 4, g = (rem & 15) << 2;
        const float* src = (p == 0) ? g_qsT : g_qcT;
        *(float4*)&qTs[(p*64 + d)*64 + g] = *(const float4*)&src[(size_t)(bh*HDIM + d)*SEQ + q0 + g];
    }

    const int p  = tid >> 7;          // path
    const int rg = (tid & 127) >> 3;  // 16 row groups of 4 q
    const int cg = tid & 7;           // 8 col groups of 8 s

    float mrun[4], lrun[4], bsc[4];
    int   bix[4];
#pragma unroll
    for (int i = 0; i < 4; i++) { mrun[i] = -FLTMAX; lrun[i] = 0.f; bsc[i] = -FLTMAX; bix[i] = 0; }

    const int qg = tid >> 4;          // PV: 16 groups of 4 q rows
    const int dg = tid & 15;          // PV: 16 groups of 4 dims
    float acc[4][4];
#pragma unroll
    for (int i = 0; i < 4; i++)
#pragma unroll
        for (int j = 0; j < 4; j++) acc[i][j] = 0.f;

    for (int s0 = 0; s0 < SEQ; s0 += 64) {
        __syncthreads();   // prev PV done before overwriting kT/vt/wt
        // load k tiles (both paths, [p][d][s]) and v tile ([s][d], pad 68)
        for (int i = tid; i < 2048; i += 256) {
            int pp = i >> 10, rem = i & 1023;
            int d = rem >> 4, g = (rem & 15) << 2;
            const float* src = (pp == 0) ? g_ksT : g_kcT;
            *(float4*)&kTs[(pp*64 + d)*64 + g] = *(const float4*)&src[(size_t)(bh*HDIM + d)*SEQ + s0 + g];
        }
        for (int i = tid; i < 1024; i += 256) {
            int r = i >> 4, d4 = (i & 15) << 2;
            *(float4*)&vts[r*68 + d4] = *(const float4*)&g_v[(size_t)((s0 + r)*BSZ + b)*EMB + h*HDIM + d4];
        }
        __syncthreads();

        // ---- scores: 4q x 8s per thread ----
        float sc[4][8];
#pragma unroll
        for (int i = 0; i < 4; i++)
#pragma unroll
            for (int j = 0; j < 8; j++) sc[i][j] = 0.f;

        const float* qbase = &qTs[p*4096 + (rg<<2)];
        const float* kbase = &kTs[p*4096 + (cg<<3)];
#pragma unroll 8
        for (int d = 0; d < 64; d++) {
            float4 qa = *(const float4*)(qbase + d*64);
            float4 k0 = *(const float4*)(kbase + d*64);
            float4 k1 = *(const float4*)(kbase + d*64 + 4);
            float av[4] = {qa.x, qa.y, qa.z, qa.w};
            float bb[8] = {k0.x, k0.y, k0.z, k0.w, k1.x, k1.y, k1.z, k1.w};
#pragma unroll
            for (int i = 0; i < 4; i++)
#pragma unroll
                for (int j = 0; j < 8; j++) sc[i][j] = fmaf(av[i], bb[j], sc[i][j]);
        }

        // mask
#pragma unroll
        for (int i = 0; i < 4; i++) {
            const float* mrow = &sem_map[(size_t)(q0 + (rg<<2) + i)*SEQ + s0 + (cg<<3)];
            float4 m0 = *(const float4*)(mrow);
            float4 m1 = *(const float4*)(mrow + 4);
            float mm[8] = {m0.x, m0.y, m0.z, m0.w, m1.x, m1.y, m1.z, m1.w};
#pragma unroll
            for (int j = 0; j < 8; j++)
                if (mm[j] < 0.5f) sc[i][j] = -FLTMAX;
        }

        if (p == 0) {  // SCA: online softmax, write weights [q][s] + fac
            float w[4][8];
#pragma unroll
            for (int i = 0; i < 4; i++) {
                float tm = sc[i][0];
#pragma unroll
                for (int j = 1; j < 8; j++) tm = fmaxf(tm, sc[i][j]);
#pragma unroll
                for (int off = 1; off < 8; off <<= 1)
                    tm = fmaxf(tm, __shfl_xor_sync(0xffffffffu, tm, off, 8));
                float mnew = fmaxf(mrun[i], tm);
                float fac  = __expf(mrun[i] - mnew);
                float sum = 0.f;
#pragma unroll
                for (int j = 0; j < 8; j++) { w[i][j] = __expf(sc[i][j] - mnew); sum += w[i][j]; }
#pragma unroll
                for (int off = 1; off < 8; off <<= 1)
                    sum += __shfl_xor_sync(0xffffffffu, sum, off, 8);
                lrun[i] = lrun[i] * fac + sum;
                mrun[i] = mnew;
                if (cg == 0) sfac[(rg<<2) + i] = fac;
                *(float4*)&wts[((rg<<2) + i)*68 + (cg<<3)]     = make_float4(w[i][0], w[i][1], w[i][2], w[i][3]);
                *(float4*)&wts[((rg<<2) + i)*68 + (cg<<3) + 4] = make_float4(w[i][4], w[i][5], w[i][6], w[i][7]);
            }
        } else {       // SSA: running argmax (first max wins)
#pragma unroll
            for (int i = 0; i < 4; i++)
#pragma unroll
                for (int j = 0; j < 8; j++) {
                    float v = sc[i][j];
                    if (v > bsc[i]) { bsc[i] = v; bix[i] = s0 + (cg<<3) + j; }
                }
        }
        __syncthreads();

        // ---- PV: 4q x 4d per thread ----
        {
            float f0 = sfac[(qg<<2) + 0], f1 = sfac[(qg<<2) + 1];
            float f2 = sfac[(qg<<2) + 2], f3 = sfac[(qg<<2) + 3];
#pragma unroll
            for (int j = 0; j < 4; j++) { acc[0][j] *= f0; acc[1][j] *= f1; acc[2][j] *= f2; acc[3][j] *= f3; }
#pragma unroll 8
            for (int s = 0; s < 64; s++) {
                float4 vv = *(const float4*)&vts[s*68 + (dg<<2)];
                float w0 = wts[((qg<<2)+0)*68 + s];
                float w1 = wts[((qg<<2)+1)*68 + s];
                float w2 = wts[((qg<<2)+2)*68 + s];
                float w3 = wts[((qg<<2)+3)*68 + s];
                acc[0][0] = fmaf(w0, vv.x, acc[0][0]); acc[0][1] = fmaf(w0, vv.y, acc[0][1]);
                acc[0][2] = fmaf(w0, vv.z, acc[0][2]); acc[0][3] = fmaf(w0, vv.w, acc[0][3]);
                acc[1][0] = fmaf(w1, vv.x, acc[1][0]); acc[1][1] = fmaf(w1, vv.y, acc[1][1]);
                acc[1][2] = fmaf(w1, vv.z, acc[1][2]); acc[1][3] = fmaf(w1, vv.w, acc[1][3]);
                acc[2][0] = fmaf(w2, vv.x, acc[2][0]); acc[2][1] = fmaf(w2, vv.y, acc[2][1]);
                acc[2][2] = fmaf(w2, vv.z, acc[2][2]); acc[2][3] = fmaf(w2, vv.w, acc[2][3]);
                acc[3][0] = fmaf(w3, vv.x, acc[3][0]); acc[3][1] = fmaf(w3, vv.y, acc[3][1]);
                acc[3][2] = fmaf(w3, vv.z, acc[3][2]); acc[3][3] = fmaf(w3, vv.w, acc[3][3]);
            }
        }
    }

    // finalize row stats
    if (p == 0) {
        if (cg == 0) {
#pragma unroll
            for (int i = 0; i < 4; i++) sl[(rg<<2) + i] = lrun[i];
        }
    } else {
#pragma unroll
        for (int i = 0; i < 4; i++) {
            float bs = bsc[i]; int bi = bix[i];
#pragma unroll
            for (int off = 1; off < 8; off <<= 1) {
                float os = __shfl_xor_sync(0xffffffffu, bs, off, 8);
                int   oi = __shfl_xor_sync(0xffffffffu, bi, off, 8);
                if (os > bs || (os == bs && oi < bi)) { bs = os; bi = oi; }
            }
            if (cg == 0) sbix[(rg<<2) + i] = bi;
        }
    }
    __syncthreads();

    // combine: T1 * (acc/l) + T2 * v[argmax]
#pragma unroll
    for (int i = 0; i < 4; i++) {
        int qr = (qg<<2) + i;
        float rl = 1.0f / sl[qr];
        int   bi = sbix[qr];
        float4 va = *(const float4*)&g_v[(size_t)(bi*BSZ + b)*EMB + h*HDIM + (dg<<2)];
        float4 o;
        o.x = T1C*acc[i][0]*rl + T2C*va.x;
        o.y = T1C*acc[i][1]*rl + T2C*va.y;
        o.z = T1C*acc[i][2]*rl + T2C*va.z;
        o.w = T1C*acc[i][3]*rl + T2C*va.w;
        *(float4*)&Ocomb[(size_t)((q0 + qr)*BSZ + b)*EMB + h*HDIM + (dg<<2)] = o;
    }
}

// -------------------------------------------------------------------------------
extern "C" void kernel_launch(void* const* d_in, const int* in_sizes, int n_in,
                              void* d_out, int out_size) {
    const float* query = (const float*)d_in[0];
    const float* key   = (const float*)d_in[1];
    const float* value = (const float*)d_in[2];
    const float* qsem  = (const float*)d_in[3];
    const float* ksem  = (const float*)d_in[4];
    const float* smap  = (const float*)d_in[5];
    const float* Wi    = (const float*)d_in[6];
    const float* bi    = (const float*)d_in[7];
    const float* Wo    = (const float*)d_in[8];
    const float* bo    = (const float*)d_in[9];
    float* out = (float*)d_out;

    float *p_qs, *p_ks, *p_qc, *p_kc, *p_v, *p_qsT, *p_ksT, *p_qcT, *p_kcT, *p_o;
    cudaGetSymbolAddress((void**)&p_qs,  g_qs);
    cudaGetSymbolAddress((void**)&p_ks,  g_ks);
    cudaGetSymbolAddress((void**)&p_qc,  g_qc);
    cudaGetSymbolAddress((void**)&p_kc,  g_kc);
    cudaGetSymbolAddress((void**)&p_v,   g_v);
    cudaGetSymbolAddress((void**)&p_qsT, g_qsT);
    cudaGetSymbolAddress((void**)&p_ksT, g_ksT);
    cudaGetSymbolAddress((void**)&p_qcT, g_qcT);
    cudaGetSymbolAddress((void**)&p_kcT, g_kcT);
    cudaGetSymbolAddress((void**)&p_o,   g_o);

    static int smem_set = 0;
    const int smem_bytes = SM_FLOATS * 4;
    if (!smem_set) {
        cudaFuncSetAttribute(attn_kernel, cudaFuncAttributeMaxDynamicSharedMemorySize, smem_bytes);
        smem_set = 1;
    }

    dim3 ggrid(EMB/64, NROWS/64);
    gemm_bias<<<ggrid, 256>>>(qsem,  Wi,               bi,        p_qs, 1.0f);
    gemm_bias<<<ggrid, 256>>>(ksem,  Wi + 512*EMB,     bi + 512,  p_ks, 1.0f);
    gemm_bias<<<ggrid, 256>>>(query, Wi,               bi,        p_qc, 1.0f);
    gemm_bias<<<ggrid, 256>>>(key,   Wi + 512*EMB,     bi + 512,  p_kc, 1.0f);
    gemm_bias<<<ggrid, 256>>>(value, Wi + 1024*EMB,    bi + 1024, p_v,  1.0f);

    dim3 tgrid(SEQ/32, HDIM/32, NBH), tblk(32, 8);
    transpose_head<<<tgrid, tblk>>>(p_qs, p_qsT, 0.125f);
    transpose_head<<<tgrid, tblk>>>(p_ks, p_ksT, 1.0f);
    transpose_head<<<tgrid, tblk>>>(p_qc, p_qcT, 0.125f);
    transpose_head<<<tgrid, tblk>>>(p_kc, p_kcT, 1.0f);

    attn_kernel<<<dim3(SEQ/64, NBH), 256, smem_bytes>>>(smap, p_o);

    gemm_bias<<<ggrid, 256>>>(p_o, Wo, bo, out, T1C + T2C);
}

// round 3
// speedup vs baseline: 1.5195x; 1.1374x over previous
#include <cuda_runtime.h>
#include <math.h>

#define SEQ   1024
#define BSZ   8
#define EMB   512
#define NHEAD 8
#define HDIM  64
#define NROWS (SEQ*BSZ)      // 8192
#define NBH   (BSZ*NHEAD)    // 64
#define FLTMAX 3.402823466e38f
#define T1C 0.6f
#define T2C 0.4f

typedef unsigned long long ull;

// ---------------- packed f32x2 helpers (sm_100+ PTX) ---------------------------
__device__ __forceinline__ ull pack2(float x, float y) {
    ull r; asm("mov.b64 %0, {%1, %2};" : "=l"(r) : "f"(x), "f"(y)); return r;
}
__device__ __forceinline__ ull dup2(float x) { return pack2(x, x); }
__device__ __forceinline__ void fma2(ull& d, ull a, ull b) {
    asm("fma.rn.f32x2 %0, %1, %2, %0;" : "+l"(d) : "l"(a), "l"(b));
}
__device__ __forceinline__ void mul2(ull& d, ull a) {
    asm("mul.rn.f32x2 %0, %0, %1;" : "+l"(d) : "l"(a));
}
__device__ __forceinline__ void unpack2(ull v, float& lo, float& hi) {
    asm("mov.b64 {%0, %1}, %2;" : "=f"(lo), "=f"(hi) : "l"(v));
}

// ---------------- scratch (device globals; no allocation allowed) -------------
__device__ float g_qs [NROWS*EMB];
__device__ float g_ks [NROWS*EMB];
__device__ float g_qc [NROWS*EMB];
__device__ float g_kc [NROWS*EMB];
__device__ float g_v  [NROWS*EMB];
__device__ float g_qsT[NBH*HDIM*SEQ];   // [bh][d][t], q pre-scaled by 1/8
__device__ float g_ksT[NBH*HDIM*SEQ];
__device__ float g_qcT[NBH*HDIM*SEQ];
__device__ float g_kcT[NBH*HDIM*SEQ];
__device__ float g_o  [NROWS*EMB];

// -------- fp32 GEMM (FFMA2): C[M,512] = X[M,512] @ W[512,512]^T + bias*bs ------
// 128x64 block tile, 256 threads, 8M x 4N per thread, acc pairs along M.
__global__ __launch_bounds__(256)
void gemm_bias(const float* __restrict__ X, const float* __restrict__ W,
               const float* __restrict__ bias, float* __restrict__ C, float bscale) {
    __shared__ float As[16][132];   // [k][m]  (m pairs 16B-aligned: 132 = 4*33)
    __shared__ float Bs[16][68];    // [k][n]
    const int bm = blockIdx.y << 7;
    const int bn = blockIdx.x << 6;
    const int tid = threadIdx.x;
    const int mg = tid >> 4;        // 16 groups * 8 rows
    const int ng = tid & 15;        // 16 groups * 4 cols
    const int ar = tid >> 2;        // fill row 0..63
    const int af = (tid & 3) << 2;  // fill k offset (float4)

    ull acc2[4][4];
#pragma unroll
    for (int p = 0; p < 4; p++)
#pragma unroll
        for (int j = 0; j < 4; j++) acc2[p][j] = 0ull;

    const float* xp0 = X + (size_t)(bm + ar) * EMB + af;
    const float* xp1 = X + (size_t)(bm + ar + 64) * EMB + af;
    const float* wp  = W + (size_t)(bn + ar) * EMB + af;

    for (int k0 = 0; k0 < EMB; k0 += 16) {
        float4 xa0 = *(const float4*)(xp0 + k0);
        float4 xa1 = *(const float4*)(xp1 + k0);
        float4 wb  = *(const float4*)(wp  + k0);
        __syncthreads();
        As[af+0][ar] = xa0.x; As[af+1][ar] = xa0.y; As[af+2][ar] = xa0.z; As[af+3][ar] = xa0.w;
        As[af+0][ar+64] = xa1.x; As[af+1][ar+64] = xa1.y; As[af+2][ar+64] = xa1.z; As[af+3][ar+64] = xa1.w;
        Bs[af+0][ar] = wb.x; Bs[af+1][ar] = wb.y; Bs[af+2][ar] = wb.z; Bs[af+3][ar] = wb.w;
        __syncthreads();
#pragma unroll
        for (int k = 0; k < 16; k++) {
            ulonglong2 a01 = *(const ulonglong2*)&As[k][mg << 3];
            ulonglong2 a23 = *(const ulonglong2*)&As[k][(mg << 3) + 4];
            float4 bv = *(const float4*)&Bs[k][ng << 2];
            ull bd0 = dup2(bv.x), bd1 = dup2(bv.y), bd2 = dup2(bv.z), bd3 = dup2(bv.w);
            fma2(acc2[0][0], a01.x, bd0); fma2(acc2[0][1], a01.x, bd1);
            fma2(acc2[0][2], a01.x, bd2); fma2(acc2[0][3], a01.x, bd3);
            fma2(acc2[1][0], a01.y, bd0); fma2(acc2[1][1], a01.y, bd1);
            fma2(acc2[1][2], a01.y, bd2); fma2(acc2[1][3], a01.y, bd3);
            fma2(acc2[2][0], a23.x, bd0); fma2(acc2[2][1], a23.x, bd1);
            fma2(acc2[2][2], a23.x, bd2); fma2(acc2[2][3], a23.x, bd3);
            fma2(acc2[3][0], a23.y, bd0); fma2(acc2[3][1], a23.y, bd1);
            fma2(acc2[3][2], a23.y, bd2); fma2(acc2[3][3], a23.y, bd3);
        }
    }

    float b0 = bias[bn + (ng<<2) + 0] * bscale;
    float b1 = bias[bn + (ng<<2) + 1] * bscale;
    float b2 = bias[bn + (ng<<2) + 2] * bscale;
    float b3 = bias[bn + (ng<<2) + 3] * bscale;
#pragma unroll
    for (int p = 0; p < 4; p++) {
        float l0, h0, l1, h1, l2, h2, l3, h3;
        unpack2(acc2[p][0], l0, h0); unpack2(acc2[p][1], l1, h1);
        unpack2(acc2[p][2], l2, h2); unpack2(acc2[p][3], l3, h3);
        int r0 = bm + (mg << 3) + (p << 1);
        float4 o0 = make_float4(l0 + b0, l1 + b1, l2 + b2, l3 + b3);
        float4 o1 = make_float4(h0 + b0, h1 + b1, h2 + b2, h3 + b3);
        *(float4*)&C[(size_t)r0 * EMB + bn + (ng<<2)]       = o0;
        *(float4*)&C[(size_t)(r0+1) * EMB + bn + (ng<<2)]   = o1;
    }
}

// ------- head transpose: out[bh][d][t] = in[t][b][h*64+d] * scale --------------
__global__ __launch_bounds__(256)
void transpose_head(const float* __restrict__ in, float* __restrict__ out, float scale) {
    __shared__ float tile[32][33];
    const int bh = blockIdx.z, b = bh >> 3, h = bh & 7;
    const int t0 = blockIdx.x << 5;
    const int d0 = blockIdx.y << 5;
    const int tx = threadIdx.x, ty = threadIdx.y;   // 32 x 8
#pragma unroll
    for (int i = 0; i < 32; i += 8)
        tile[ty + i][tx] = in[(size_t)(t0 + ty + i) * (BSZ*EMB) + b * EMB + h * HDIM + d0 + tx] * scale;
    __syncthreads();
#pragma unroll
    for (int i = 0; i < 32; i += 8)
        out[(size_t)(bh * HDIM + d0 + ty + i) * SEQ + t0 + tx] = tile[tx][ty + i];
}

// ---------------- fused dual-path attention (64q x 64s tiles, FFMA2) -----------
#define SM_QT   0
#define SM_KT   8192
#define SM_VT   16384
#define SM_WT   (16384 + 64*68)
#define SM_FAC  (16384 + 2*64*68)
#define SM_L    (SM_FAC + 64)
#define SM_BIX  (SM_L + 64)
#define SM_FLOATS (SM_BIX + 64)

__global__ __launch_bounds__(256, 2)
void attn_kernel(const float* __restrict__ sem_map, float* __restrict__ Ocomb) {
    extern __shared__ float sm[];
    float* qTs  = sm + SM_QT;
    float* kTs  = sm + SM_KT;
    float* vts  = sm + SM_VT;
    float* wts  = sm + SM_WT;
    float* sfac = sm + SM_FAC;
    float* sl   = sm + SM_L;
    int*   sbix = (int*)(sm + SM_BIX);

    const int bh = blockIdx.y, b = bh >> 3, h = bh & 7;
    const int q0 = blockIdx.x << 6;
    const int tid = threadIdx.x;

    // q tiles (both paths), layout [p][d][q]
    for (int i = tid; i < 2048; i += 256) {
        int p = i >> 10, rem = i & 1023;
        int d = rem >> 4, g = (rem & 15) << 2;
        const float* src = (p == 0) ? g_qsT : g_qcT;
        *(float4*)&qTs[(p*64 + d)*64 + g] = *(const float4*)&src[(size_t)(bh*HDIM + d)*SEQ + q0 + g];
    }

    const int p  = tid >> 7;          // path
    const int rg = (tid & 127) >> 3;  // 16 row groups of 4 q
    const int cg = tid & 7;           // 8 col groups of 8 s

    float mrun[4], lrun[4], bsc[4];
    int   bix[4];
#pragma unroll
    for (int i = 0; i < 4; i++) { mrun[i] = -FLTMAX; lrun[i] = 0.f; bsc[i] = -FLTMAX; bix[i] = 0; }

    const int qg = tid >> 4;          // PV: 16 groups of 4 q rows
    const int dg = tid & 15;          // PV: 16 groups of 4 dims (2 pairs)
    ull acc2[4][2];
#pragma unroll
    for (int i = 0; i < 4; i++) { acc2[i][0] = 0ull; acc2[i][1] = 0ull; }

    const float* qbase = &qTs[p*4096 + (rg<<2)];
    const float* kbase = &kTs[p*4096 + (cg<<3)];

    for (int s0 = 0; s0 < SEQ; s0 += 64) {
        __syncthreads();   // prev PV done before overwriting kT/vt/wt
        for (int i = tid; i < 2048; i += 256) {
            int pp = i >> 10, rem = i & 1023;
            int d = rem >> 4, g = (rem & 15) << 2;
            const float* src = (pp == 0) ? g_ksT : g_kcT;
            *(float4*)&kTs[(pp*64 + d)*64 + g] = *(const float4*)&src[(size_t)(bh*HDIM + d)*SEQ + s0 + g];
        }
        for (int i = tid; i < 1024; i += 256) {
            int r = i >> 4, d4 = (i & 15) << 2;
            *(float4*)&vts[r*68 + d4] = *(const float4*)&g_v[(size_t)((s0 + r)*BSZ + b)*EMB + h*HDIM + d4];
        }
        __syncthreads();

        // ---- scores: 4q x 8s per thread, acc pairs along s ----
        ull sc2[4][4];
#pragma unroll
        for (int i = 0; i < 4; i++)
#pragma unroll
            for (int j = 0; j < 4; j++) sc2[i][j] = 0ull;

#pragma unroll 8
        for (int d = 0; d < 64; d++) {
            float4 qa = *(const float4*)(qbase + d*64);
            ulonglong2 k01 = *(const ulonglong2*)(kbase + d*64);
            ulonglong2 k23 = *(const ulonglong2*)(kbase + d*64 + 4);
            ull q0d = dup2(qa.x), q1d = dup2(qa.y), q2d = dup2(qa.z), q3d = dup2(qa.w);
            fma2(sc2[0][0], q0d, k01.x); fma2(sc2[0][1], q0d, k01.y);
            fma2(sc2[0][2], q0d, k23.x); fma2(sc2[0][3], q0d, k23.y);
            fma2(sc2[1][0], q1d, k01.x); fma2(sc2[1][1], q1d, k01.y);
            fma2(sc2[1][2], q1d, k23.x); fma2(sc2[1][3], q1d, k23.y);
            fma2(sc2[2][0], q2d, k01.x); fma2(sc2[2][1], q2d, k01.y);
            fma2(sc2[2][2], q2d, k23.x); fma2(sc2[2][3], q2d, k23.y);
            fma2(sc2[3][0], q3d, k01.x); fma2(sc2[3][1], q3d, k01.y);
            fma2(sc2[3][2], q3d, k23.x); fma2(sc2[3][3], q3d, k23.y);
        }

        float sc[4][8];
#pragma unroll
        for (int i = 0; i < 4; i++)
#pragma unroll
            for (int j = 0; j < 4; j++) unpack2(sc2[i][j], sc[i][2*j], sc[i][2*j+1]);

        // mask
#pragma unroll
        for (int i = 0; i < 4; i++) {
            const float* mrow = &sem_map[(size_t)(q0 + (rg<<2) + i)*SEQ + s0 + (cg<<3)];
            float4 m0 = *(const float4*)(mrow);
            float4 m1 = *(const float4*)(mrow + 4);
            float mm[8] = {m0.x, m0.y, m0.z, m0.w, m1.x, m1.y, m1.z, m1.w};
#pragma unroll
            for (int j = 0; j < 8; j++)
                if (mm[j] < 0.5f) sc[i][j] = -FLTMAX;
        }

        if (p == 0) {  // SCA: online softmax
            float w[4][8];
#pragma unroll
            for (int i = 0; i < 4; i++) {
                float tm = sc[i][0];
#pragma unroll
                for (int j = 1; j < 8; j++) tm = fmaxf(tm, sc[i][j]);
#pragma unroll
                for (int off = 1; off < 8; off <<= 1)
                    tm = fmaxf(tm, __shfl_xor_sync(0xffffffffu, tm, off, 8));
                float mnew = fmaxf(mrun[i], tm);
                float fac  = __expf(mrun[i] - mnew);
                float sum = 0.f;
#pragma unroll
                for (int j = 0; j < 8; j++) { w[i][j] = __expf(sc[i][j] - mnew); sum += w[i][j]; }
#pragma unroll
                for (int off = 1; off < 8; off <<= 1)
                    sum += __shfl_xor_sync(0xffffffffu, sum, off, 8);
                lrun[i] = lrun[i] * fac + sum;
                mrun[i] = mnew;
                if (cg == 0) sfac[(rg<<2) + i] = fac;
                *(float4*)&wts[((rg<<2) + i)*68 + (cg<<3)]     = make_float4(w[i][0], w[i][1], w[i][2], w[i][3]);
                *(float4*)&wts[((rg<<2) + i)*68 + (cg<<3) + 4] = make_float4(w[i][4], w[i][5], w[i][6], w[i][7]);
            }
        } else {       // SSA: running argmax (first max wins)
#pragma unroll
            for (int i = 0; i < 4; i++)
#pragma unroll
                for (int j = 0; j < 8; j++) {
                    float v = sc[i][j];
                    if (v > bsc[i]) { bsc[i] = v; bix[i] = s0 + (cg<<3) + j; }
                }
        }
        __syncthreads();

        // ---- PV: 4q x 4d per thread, acc pairs along d ----
        {
            ull f0 = dup2(sfac[(qg<<2) + 0]);
            ull f1 = dup2(sfac[(qg<<2) + 1]);
            ull f2 = dup2(sfac[(qg<<2) + 2]);
            ull f3 = dup2(sfac[(qg<<2) + 3]);
            mul2(acc2[0][0], f0); mul2(acc2[0][1], f0);
            mul2(acc2[1][0], f1); mul2(acc2[1][1], f1);
            mul2(acc2[2][0], f2); mul2(acc2[2][1], f2);
            mul2(acc2[3][0], f3); mul2(acc2[3][1], f3);
#pragma unroll 8
            for (int s = 0; s < 64; s++) {
                ulonglong2 vv = *(const ulonglong2*)&vts[s*68 + (dg<<2)];
                ull w0 = dup2(wts[((qg<<2)+0)*68 + s]);
                ull w1 = dup2(wts[((qg<<2)+1)*68 + s]);
                ull w2 = dup2(wts[((qg<<2)+2)*68 + s]);
                ull w3 = dup2(wts[((qg<<2)+3)*68 + s]);
                fma2(acc2[0][0], w0, vv.x); fma2(acc2[0][1], w0, vv.y);
                fma2(acc2[1][0], w1, vv.x); fma2(acc2[1][1], w1, vv.y);
                fma2(acc2[2][0], w2, vv.x); fma2(acc2[2][1], w2, vv.y);
                fma2(acc2[3][0], w3, vv.x); fma2(acc2[3][1], w3, vv.y);
            }
        }
    }

    // finalize row stats
    if (p == 0) {
        if (cg == 0) {
#pragma unroll
            for (int i = 0; i < 4; i++) sl[(rg<<2) + i] = lrun[i];
        }
    } else {
#pragma unroll
        for (int i = 0; i < 4; i++) {
            float bs = bsc[i]; int bi = bix[i];
#pragma unroll
            for (int off = 1; off < 8; off <<= 1) {
                float os = __shfl_xor_sync(0xffffffffu, bs, off, 8);
                int   oi = __shfl_xor_sync(0xffffffffu, bi, off, 8);
                if (os > bs || (os == bs && oi < bi)) { bs = os; bi = oi; }
            }
            if (cg == 0) sbix[(rg<<2) + i] = bi;
        }
    }
    __syncthreads();

    // combine: T1 * (acc/l) + T2 * v[argmax]
#pragma unroll
    for (int i = 0; i < 4; i++) {
        int qr = (qg<<2) + i;
        float rl = 1.0f / sl[qr];
        int   bi = sbix[qr];
        float4 va = *(const float4*)&g_v[(size_t)(bi*BSZ + b)*EMB + h*HDIM + (dg<<2)];
        float a0, a1, a2, a3;
        unpack2(acc2[i][0], a0, a1);
        unpack2(acc2[i][1], a2, a3);
        float4 o;
        o.x = T1C*a0*rl + T2C*va.x;
        o.y = T1C*a1*rl + T2C*va.y;
        o.z = T1C*a2*rl + T2C*va.z;
        o.w = T1C*a3*rl + T2C*va.w;
        *(float4*)&Ocomb[(size_t)((q0 + qr)*BSZ + b)*EMB + h*HDIM + (dg<<2)] = o;
    }
}

// -------------------------------------------------------------------------------
extern "C" void kernel_launch(void* const* d_in, const int* in_sizes, int n_in,
                              void* d_out, int out_size) {
    const float* query = (const float*)d_in[0];
    const float* key   = (const float*)d_in[1];
    const float* value = (const float*)d_in[2];
    const float* qsem  = (const float*)d_in[3];
    const float* ksem  = (const float*)d_in[4];
    const float* smap  = (const float*)d_in[5];
    const float* Wi    = (const float*)d_in[6];
    const float* bi    = (const float*)d_in[7];
    const float* Wo    = (const float*)d_in[8];
    const float* bo    = (const float*)d_in[9];
    float* out = (float*)d_out;

    float *p_qs, *p_ks, *p_qc, *p_kc, *p_v, *p_qsT, *p_ksT, *p_qcT, *p_kcT, *p_o;
    cudaGetSymbolAddress((void**)&p_qs,  g_qs);
    cudaGetSymbolAddress((void**)&p_ks,  g_ks);
    cudaGetSymbolAddress((void**)&p_qc,  g_qc);
    cudaGetSymbolAddress((void**)&p_kc,  g_kc);
    cudaGetSymbolAddress((void**)&p_v,   g_v);
    cudaGetSymbolAddress((void**)&p_qsT, g_qsT);
    cudaGetSymbolAddress((void**)&p_ksT, g_ksT);
    cudaGetSymbolAddress((void**)&p_qcT, g_qcT);
    cudaGetSymbolAddress((void**)&p_kcT, g_kcT);
    cudaGetSymbolAddress((void**)&p_o,   g_o);

    static int smem_set = 0;
    const int smem_bytes = SM_FLOATS * 4;
    if (!smem_set) {
        cudaFuncSetAttribute(attn_kernel, cudaFuncAttributeMaxDynamicSharedMemorySize, smem_bytes);
        smem_set = 1;
    }

    dim3 ggrid(EMB/64, NROWS/128);
    gemm_bias<<<ggrid, 256>>>(qsem,  Wi,               bi,        p_qs, 1.0f);
    gemm_bias<<<ggrid, 256>>>(ksem,  Wi + 512*EMB,     bi + 512,  p_ks, 1.0f);
    gemm_bias<<<ggrid, 256>>>(query, Wi,               bi,        p_qc, 1.0f);
    gemm_bias<<<ggrid, 256>>>(key,   Wi + 512*EMB,     bi + 512,  p_kc, 1.0f);
    gemm_bias<<<ggrid, 256>>>(value, Wi + 1024*EMB,    bi + 1024, p_v,  1.0f);

    dim3 tgrid(SEQ/32, HDIM/32, NBH), tblk(32, 8);
    transpose_head<<<tgrid, tblk>>>(p_qs, p_qsT, 0.125f);
    transpose_head<<<tgrid, tblk>>>(p_ks, p_ksT, 1.0f);
    transpose_head<<<tgrid, tblk>>>(p_qc, p_qcT, 0.125f);
    transpose_head<<<tgrid, tblk>>>(p_kc, p_kcT, 1.0f);

    attn_kernel<<<dim3(SEQ/64, NBH), 256, smem_bytes>>>(smap, p_o);

    gemm_bias<<<ggrid, 256>>>(p_o, Wo, bo, out, T1C + T2C);
}

// round 4
// speedup vs baseline: 1.7931x; 1.1801x over previous
#include <cuda_runtime.h>
#include <math.h>

#define SEQ   1024
#define BSZ   8
#define EMB   512
#define NHEAD 8
#define HDIM  64
#define NROWS (SEQ*BSZ)      // 8192
#define NBH   (BSZ*NHEAD)    // 64
#define FLTMAX 3.402823466e38f
#define T1C 0.6f
#define T2C 0.4f

typedef unsigned long long ull;

// ---------------- packed f32x2 helpers (sm_100+ PTX) ---------------------------
__device__ __forceinline__ ull pack2(float x, float y) {
    ull r; asm("mov.b64 %0, {%1, %2};" : "=l"(r) : "f"(x), "f"(y)); return r;
}
__device__ __forceinline__ ull dup2(float x) { return pack2(x, x); }
__device__ __forceinline__ void fma2(ull& d, ull a, ull b) {
    asm("fma.rn.f32x2 %0, %1, %2, %0;" : "+l"(d) : "l"(a), "l"(b));
}
__device__ __forceinline__ void mul2(ull& d, ull a) {
    asm("mul.rn.f32x2 %0, %0, %1;" : "+l"(d) : "l"(a));
}
__device__ __forceinline__ void unpack2(ull v, float& lo, float& hi) {
    asm("mov.b64 {%0, %1}, %2;" : "=f"(lo), "=f"(hi) : "l"(v));
}

// ---------------- scratch (device globals; no allocation allowed) -------------
__device__ float g_qs [NROWS*EMB];
__device__ float g_ks [NROWS*EMB];
__device__ float g_qc [NROWS*EMB];
__device__ float g_kc [NROWS*EMB];
__device__ float g_v  [NROWS*EMB];
__device__ float g_qsT[NBH*HDIM*SEQ];   // [bh][d][t], q pre-scaled by 1/8
__device__ float g_ksT[NBH*HDIM*SEQ];
__device__ float g_qcT[NBH*HDIM*SEQ];
__device__ float g_kcT[NBH*HDIM*SEQ];
__device__ float g_o  [NROWS*EMB];
__device__ int   g_idx[NBH*SEQ];        // SSA argmax index per (bh, q)

// ---------------- batched param structs ----------------------------------------
struct GemmBatch {
    const float* x[5];
    float*       c[5];
    int          woff[5];
};
struct TransBatch {
    const float* src[4];
    float*       dst[4];
    float        scale[4];
};

// -------- fp32 GEMM (FFMA2): C[M,512] = X[M,512] @ W[512,512]^T + bias ---------
// 128x64 block tile, 256 threads, 8M x 4N per thread, acc pairs along M.
__device__ __forceinline__ void gemm_body(const float* __restrict__ X,
                                          const float* __restrict__ W,
                                          const float* __restrict__ bias,
                                          float* __restrict__ C, float bscale) {
    __shared__ float As[16][132];
    __shared__ float Bs[16][68];
    const int bm = blockIdx.y << 7;
    const int bn = blockIdx.x << 6;
    const int tid = threadIdx.x;
    const int mg = tid >> 4;
    const int ng = tid & 15;
    const int ar = tid >> 2;
    const int af = (tid & 3) << 2;

    ull acc2[4][4];
#pragma unroll
    for (int p = 0; p < 4; p++)
#pragma unroll
        for (int j = 0; j < 4; j++) acc2[p][j] = 0ull;

    const float* xp0 = X + (size_t)(bm + ar) * EMB + af;
    const float* xp1 = X + (size_t)(bm + ar + 64) * EMB + af;
    const float* wp  = W + (size_t)(bn + ar) * EMB + af;

    for (int k0 = 0; k0 < EMB; k0 += 16) {
        float4 xa0 = *(const float4*)(xp0 + k0);
        float4 xa1 = *(const float4*)(xp1 + k0);
        float4 wb  = *(const float4*)(wp  + k0);
        __syncthreads();
        As[af+0][ar] = xa0.x; As[af+1][ar] = xa0.y; As[af+2][ar] = xa0.z; As[af+3][ar] = xa0.w;
        As[af+0][ar+64] = xa1.x; As[af+1][ar+64] = xa1.y; As[af+2][ar+64] = xa1.z; As[af+3][ar+64] = xa1.w;
        Bs[af+0][ar] = wb.x; Bs[af+1][ar] = wb.y; Bs[af+2][ar] = wb.z; Bs[af+3][ar] = wb.w;
        __syncthreads();
#pragma unroll
        for (int k = 0; k < 16; k++) {
            ulonglong2 a01 = *(const ulonglong2*)&As[k][mg << 3];
            ulonglong2 a23 = *(const ulonglong2*)&As[k][(mg << 3) + 4];
            float4 bv = *(const float4*)&Bs[k][ng << 2];
            ull bd0 = dup2(bv.x), bd1 = dup2(bv.y), bd2 = dup2(bv.z), bd3 = dup2(bv.w);
            fma2(acc2[0][0], a01.x, bd0); fma2(acc2[0][1], a01.x, bd1);
            fma2(acc2[0][2], a01.x, bd2); fma2(acc2[0][3], a01.x, bd3);
            fma2(acc2[1][0], a01.y, bd0); fma2(acc2[1][1], a01.y, bd1);
            fma2(acc2[1][2], a01.y, bd2); fma2(acc2[1][3], a01.y, bd3);
            fma2(acc2[2][0], a23.x, bd0); fma2(acc2[2][1], a23.x, bd1);
            fma2(acc2[2][2], a23.x, bd2); fma2(acc2[2][3], a23.x, bd3);
            fma2(acc2[3][0], a23.y, bd0); fma2(acc2[3][1], a23.y, bd1);
            fma2(acc2[3][2], a23.y, bd2); fma2(acc2[3][3], a23.y, bd3);
        }
    }

    float b0 = bias[bn + (ng<<2) + 0] * bscale;
    float b1 = bias[bn + (ng<<2) + 1] * bscale;
    float b2 = bias[bn + (ng<<2) + 2] * bscale;
    float b3 = bias[bn + (ng<<2) + 3] * bscale;
#pragma unroll
    for (int p = 0; p < 4; p++) {
        float l0, h0, l1, h1, l2, h2, l3, h3;
        unpack2(acc2[p][0], l0, h0); unpack2(acc2[p][1], l1, h1);
        unpack2(acc2[p][2], l2, h2); unpack2(acc2[p][3], l3, h3);
        int r0 = bm + (mg << 3) + (p << 1);
        float4 o0 = make_float4(l0 + b0, l1 + b1, l2 + b2, l3 + b3);
        float4 o1 = make_float4(h0 + b0, h1 + b1, h2 + b2, h3 + b3);
        *(float4*)&C[(size_t)r0 * EMB + bn + (ng<<2)]       = o0;
        *(float4*)&C[(size_t)(r0+1) * EMB + bn + (ng<<2)]   = o1;
    }
}

__global__ __launch_bounds__(256, 3)
void gemm_bias5(GemmBatch gb, const float* __restrict__ W, const float* __restrict__ bias) {
    const int z = blockIdx.z;
    gemm_body(gb.x[z], W + (size_t)gb.woff[z] * EMB, bias + gb.woff[z], gb.c[z], 1.0f);
}

__global__ __launch_bounds__(256, 3)
void gemm_bias(const float* __restrict__ X, const float* __restrict__ W,
               const float* __restrict__ bias, float* __restrict__ C, float bscale) {
    gemm_body(X, W, bias, C, bscale);
}

// ------- head transpose x4: out[bh][d][t] = in[t][b][h*64+d] * scale -----------
__global__ __launch_bounds__(256)
void transpose_head4(TransBatch tb) {
    __shared__ float tile[32][33];
    const int z = blockIdx.z;
    const int var = z >> 6, bh = z & 63;
    const int b = bh >> 3, h = bh & 7;
    const float* in  = tb.src[var];
    float* out = tb.dst[var];
    const float scale = tb.scale[var];
    const int t0 = blockIdx.x << 5;
    const int d0 = blockIdx.y << 5;
    const int tx = threadIdx.x & 31, ty = threadIdx.x >> 5;  // 32 x 8
#pragma unroll
    for (int i = 0; i < 32; i += 8)
        tile[ty + i][tx] = in[(size_t)(t0 + ty + i) * (BSZ*EMB) + b * EMB + h * HDIM + d0 + tx] * scale;
    __syncthreads();
#pragma unroll
    for (int i = 0; i < 32; i += 8)
        out[(size_t)(bh * HDIM + d0 + ty + i) * SEQ + t0 + tx] = tile[tx][ty + i];
}

// ---------------- SSA kernel: scores + running argmax --------------------------
// 128q x 64s tiles, 256 threads: rg=tid>>4 (16 x 8q), cg=tid&15 (16 x 4s)
// smem: qT[64][128] + kT[64][64]  (layout [d][row])
#define SSA_SM_FLOATS (64*128 + 64*64)
__global__ __launch_bounds__(256, 2)
void ssa_kernel(const float* __restrict__ sem_map) {
    extern __shared__ float sm[];
    float* qTs = sm;            // [d][128]
    float* kTs = sm + 64*128;   // [d][64]

    const int bh = blockIdx.y;
    const int q0 = blockIdx.x << 7;
    const int tid = threadIdx.x;
    const int rg = tid >> 4;    // 8-q row group
    const int cg = tid & 15;    // 4-s col group

    for (int i = tid; i < 2048; i += 256) {   // 64*128/4
        int d = i >> 5, g = (i & 31) << 2;
        *(float4*)&qTs[d*128 + g] = *(const float4*)&g_qcT[(size_t)(bh*HDIM + d)*SEQ + q0 + g];
    }

    float bsc[8];
    int   bix[8];
#pragma unroll
    for (int i = 0; i < 8; i++) { bsc[i] = -FLTMAX; bix[i] = 0; }

    const float* qb = &qTs[rg << 3];
    const float* kb = &kTs[cg << 2];

    for (int s0 = 0; s0 < SEQ; s0 += 64) {
        __syncthreads();
        for (int i = tid; i < 1024; i += 256) {
            int d = i >> 4, g = (i & 15) << 2;
            *(float4*)&kTs[d*64 + g] = *(const float4*)&g_kcT[(size_t)(bh*HDIM + d)*SEQ + s0 + g];
        }
        __syncthreads();

        ull sc2[4][4];   // [q-pair][s]
#pragma unroll
        for (int i = 0; i < 4; i++)
#pragma unroll
            for (int j = 0; j < 4; j++) sc2[i][j] = 0ull;

#pragma unroll 4
        for (int d = 0; d < 64; d++) {
            ulonglong2 q01 = *(const ulonglong2*)(qb + d*128);
            ulonglong2 q23 = *(const ulonglong2*)(qb + d*128 + 4);
            float4 kv = *(const float4*)(kb + d*64);
            ull k0 = dup2(kv.x), k1 = dup2(kv.y), k2 = dup2(kv.z), k3 = dup2(kv.w);
            fma2(sc2[0][0], q01.x, k0); fma2(sc2[0][1], q01.x, k1);
            fma2(sc2[0][2], q01.x, k2); fma2(sc2[0][3], q01.x, k3);
            fma2(sc2[1][0], q01.y, k0); fma2(sc2[1][1], q01.y, k1);
            fma2(sc2[1][2], q01.y, k2); fma2(sc2[1][3], q01.y, k3);
            fma2(sc2[2][0], q23.x, k0); fma2(sc2[2][1], q23.x, k1);
            fma2(sc2[2][2], q23.x, k2); fma2(sc2[2][3], q23.x, k3);
            fma2(sc2[3][0], q23.y, k0); fma2(sc2[3][1], q23.y, k1);
            fma2(sc2[3][2], q23.y, k2); fma2(sc2[3][3], q23.y, k3);
        }

        // unpack + mask + running argmax (first/lowest index wins)
#pragma unroll
        for (int qp = 0; qp < 4; qp++) {
            float s0v[4], s1v[4];
#pragma unroll
            for (int j = 0; j < 4; j++) unpack2(sc2[qp][j], s0v[j], s1v[j]);
            int i0 = (qp << 1), i1 = i0 + 1;
            const float* m0 = &sem_map[(size_t)(q0 + (rg<<3) + i0)*SEQ + s0 + (cg<<2)];
            const float* m1 = &sem_map[(size_t)(q0 + (rg<<3) + i1)*SEQ + s0 + (cg<<2)];
            float4 mk0 = *(const float4*)m0;
            float4 mk1 = *(const float4*)m1;
            float ma[4] = {mk0.x, mk0.y, mk0.z, mk0.w};
            float mb[4] = {mk1.x, mk1.y, mk1.z, mk1.w};
#pragma unroll
            for (int j = 0; j < 4; j++) {
                float va = (ma[j] < 0.5f) ? -FLTMAX : s0v[j];
                float vb = (mb[j] < 0.5f) ? -FLTMAX : s1v[j];
                if (va > bsc[i0]) { bsc[i0] = va; bix[i0] = s0 + (cg<<2) + j; }
                if (vb > bsc[i1]) { bsc[i1] = vb; bix[i1] = s0 + (cg<<2) + j; }
            }
        }
    }

    // reduce across the 16 col-groups (contiguous lanes, width 16)
#pragma unroll
    for (int i = 0; i < 8; i++) {
        float bs = bsc[i]; int bi = bix[i];
#pragma unroll
        for (int off = 1; off < 16; off <<= 1) {
            float os = __shfl_xor_sync(0xffffffffu, bs, off, 16);
            int   oi = __shfl_xor_sync(0xffffffffu, bi, off, 16);
            if (os > bs || (os == bs && oi < bi)) { bs = os; bi = oi; }
        }
        if (cg == 0) g_idx[bh*SEQ + q0 + (rg<<3) + i] = bi;
    }
}

// ---------------- SCA kernel: softmax attention + combine ----------------------
// 64q x 64s tiles, 256 threads.
// Score: rg=tid>>4 (16 x 4q), cgs=tid&15 (16 x 4s). PV: qg=tid>>4, dgp=tid&15.
#define SCA_QT   0
#define SCA_KT   4096
#define SCA_VT   8192
#define SCA_WT   (8192 + 64*68)
#define SCA_FAC  (8192 + 2*64*68)
#define SCA_L    (SCA_FAC + 64)
#define SCA_SM_FLOATS (SCA_L + 64)

__global__ __launch_bounds__(256, 2)
void sca_kernel(const float* __restrict__ sem_map, float* __restrict__ Ocomb) {
    extern __shared__ float sm[];
    float* qTs  = sm + SCA_QT;   // [d][64]
    float* kTs  = sm + SCA_KT;   // [d][64]
    float* vts  = sm + SCA_VT;   // [s][68]
    float* wts  = sm + SCA_WT;   // [q][68]
    float* sfac = sm + SCA_FAC;
    float* sl   = sm + SCA_L;

    const int bh = blockIdx.y, b = bh >> 3, h = bh & 7;
    const int q0 = blockIdx.x << 6;
    const int tid = threadIdx.x;
    const int rg = tid >> 4;     // 4-q row group
    const int cgs = tid & 15;    // 4-s col group

    for (int i = tid; i < 1024; i += 256) {
        int d = i >> 4, g = (i & 15) << 2;
        *(float4*)&qTs[d*64 + g] = *(const float4*)&g_qsT[(size_t)(bh*HDIM + d)*SEQ + q0 + g];
    }

    float mrun[4], lrun[4];
#pragma unroll
    for (int i = 0; i < 4; i++) { mrun[i] = -FLTMAX; lrun[i] = 0.f; }

    const int qg = tid >> 4;
    const int dgp = tid & 15;
    ull acc2[4][2];
#pragma unroll
    for (int i = 0; i < 4; i++) { acc2[i][0] = 0ull; acc2[i][1] = 0ull; }

    const float* qb = &qTs[rg << 2];
    const float* kb = &kTs[cgs << 2];

    for (int s0 = 0; s0 < SEQ; s0 += 64) {
        __syncthreads();
        for (int i = tid; i < 1024; i += 256) {
            int d = i >> 4, g = (i & 15) << 2;
            *(float4*)&kTs[d*64 + g] = *(const float4*)&g_ksT[(size_t)(bh*HDIM + d)*SEQ + s0 + g];
            int r = i >> 4, d4 = (i & 15) << 2;
            *(float4*)&vts[r*68 + d4] = *(const float4*)&g_v[(size_t)((s0 + r)*BSZ + b)*EMB + h*HDIM + d4];
        }
        __syncthreads();

        // scores 4q x 4s, acc pairs along s
        ull sc2[4][2];
#pragma unroll
        for (int i = 0; i < 4; i++) { sc2[i][0] = 0ull; sc2[i][1] = 0ull; }
#pragma unroll 8
        for (int d = 0; d < 64; d++) {
            float4 qa = *(const float4*)(qb + d*64);
            ulonglong2 kk = *(const ulonglong2*)(kb + d*64);
            ull q0d = dup2(qa.x), q1d = dup2(qa.y), q2d = dup2(qa.z), q3d = dup2(qa.w);
            fma2(sc2[0][0], q0d, kk.x); fma2(sc2[0][1], q0d, kk.y);
            fma2(sc2[1][0], q1d, kk.x); fma2(sc2[1][1], q1d, kk.y);
            fma2(sc2[2][0], q2d, kk.x); fma2(sc2[2][1], q2d, kk.y);
            fma2(sc2[3][0], q3d, kk.x); fma2(sc2[3][1], q3d, kk.y);
        }

        float sc[4][4];
#pragma unroll
        for (int i = 0; i < 4; i++) {
            unpack2(sc2[i][0], sc[i][0], sc[i][1]);
            unpack2(sc2[i][1], sc[i][2], sc[i][3]);
        }
        // mask
#pragma unroll
        for (int i = 0; i < 4; i++) {
            float4 mk = *(const float4*)&sem_map[(size_t)(q0 + (rg<<2) + i)*SEQ + s0 + (cgs<<2)];
            if (mk.x < 0.5f) sc[i][0] = -FLTMAX;
            if (mk.y < 0.5f) sc[i][1] = -FLTMAX;
            if (mk.z < 0.5f) sc[i][2] = -FLTMAX;
            if (mk.w < 0.5f) sc[i][3] = -FLTMAX;
        }
        // online softmax (reduce across 16 lanes)
#pragma unroll
        for (int i = 0; i < 4; i++) {
            float tm = fmaxf(fmaxf(sc[i][0], sc[i][1]), fmaxf(sc[i][2], sc[i][3]));
#pragma unroll
            for (int off = 1; off < 16; off <<= 1)
                tm = fmaxf(tm, __shfl_xor_sync(0xffffffffu, tm, off, 16));
            float mnew = fmaxf(mrun[i], tm);
            float fac  = __expf(mrun[i] - mnew);
            float w0 = __expf(sc[i][0] - mnew);
            float w1 = __expf(sc[i][1] - mnew);
            float w2 = __expf(sc[i][2] - mnew);
            float w3 = __expf(sc[i][3] - mnew);
            float sum = (w0 + w1) + (w2 + w3);
#pragma unroll
            for (int off = 1; off < 16; off <<= 1)
                sum += __shfl_xor_sync(0xffffffffu, sum, off, 16);
            lrun[i] = lrun[i] * fac + sum;
            mrun[i] = mnew;
            if (cgs == 0) sfac[(rg<<2) + i] = fac;
            *(float4*)&wts[((rg<<2) + i)*68 + (cgs<<2)] = make_float4(w0, w1, w2, w3);
        }
        __syncthreads();

        // PV: 4q x 4d per thread, acc pairs along d
        {
            ull f0 = dup2(sfac[(qg<<2) + 0]);
            ull f1 = dup2(sfac[(qg<<2) + 1]);
            ull f2 = dup2(sfac[(qg<<2) + 2]);
            ull f3 = dup2(sfac[(qg<<2) + 3]);
            mul2(acc2[0][0], f0); mul2(acc2[0][1], f0);
            mul2(acc2[1][0], f1); mul2(acc2[1][1], f1);
            mul2(acc2[2][0], f2); mul2(acc2[2][1], f2);
            mul2(acc2[3][0], f3); mul2(acc2[3][1], f3);
#pragma unroll 8
            for (int s = 0; s < 64; s++) {
                ulonglong2 vv = *(const ulonglong2*)&vts[s*68 + (dgp<<2)];
                ull w0 = dup2(wts[((qg<<2)+0)*68 + s]);
                ull w1 = dup2(wts[((qg<<2)+1)*68 + s]);
                ull w2 = dup2(wts[((qg<<2)+2)*68 + s]);
                ull w3 = dup2(wts[((qg<<2)+3)*68 + s]);
                fma2(acc2[0][0], w0, vv.x); fma2(acc2[0][1], w0, vv.y);
                fma2(acc2[1][0], w1, vv.x); fma2(acc2[1][1], w1, vv.y);
                fma2(acc2[2][0], w2, vv.x); fma2(acc2[2][1], w2, vv.y);
                fma2(acc2[3][0], w3, vv.x); fma2(acc2[3][1], w3, vv.y);
            }
        }
    }

    if (cgs == 0) {
#pragma unroll
        for (int i = 0; i < 4; i++) sl[(rg<<2) + i] = lrun[i];
    }
    __syncthreads();

    // combine: T1 * (acc/l) + T2 * v[g_idx]
#pragma unroll
    for (int i = 0; i < 4; i++) {
        int qr = (qg<<2) + i;
        float rl = 1.0f / sl[qr];
        int   bi = g_idx[bh*SEQ + q0 + qr];
        float4 va = *(const float4*)&g_v[(size_t)(bi*BSZ + b)*EMB + h*HDIM + (dgp<<2)];
        float a0, a1, a2, a3;
        unpack2(acc2[i][0], a0, a1);
        unpack2(acc2[i][1], a2, a3);
        float4 o;
        o.x = T1C*a0*rl + T2C*va.x;
        o.y = T1C*a1*rl + T2C*va.y;
        o.z = T1C*a2*rl + T2C*va.z;
        o.w = T1C*a3*rl + T2C*va.w;
        *(float4*)&Ocomb[(size_t)((q0 + qr)*BSZ + b)*EMB + h*HDIM + (dgp<<2)] = o;
    }
}

// -------------------------------------------------------------------------------
extern "C" void kernel_launch(void* const* d_in, const int* in_sizes, int n_in,
                              void* d_out, int out_size) {
    const float* query = (const float*)d_in[0];
    const float* key   = (const float*)d_in[1];
    const float* value = (const float*)d_in[2];
    const float* qsem  = (const float*)d_in[3];
    const float* ksem  = (const float*)d_in[4];
    const float* smap  = (const float*)d_in[5];
    const float* Wi    = (const float*)d_in[6];
    const float* bi    = (const float*)d_in[7];
    const float* Wo    = (const float*)d_in[8];
    const float* bo    = (const float*)d_in[9];
    float* out = (float*)d_out;

    float *p_qs, *p_ks, *p_qc, *p_kc, *p_v, *p_qsT, *p_ksT, *p_qcT, *p_kcT, *p_o;
    cudaGetSymbolAddress((void**)&p_qs,  g_qs);
    cudaGetSymbolAddress((void**)&p_ks,  g_ks);
    cudaGetSymbolAddress((void**)&p_qc,  g_qc);
    cudaGetSymbolAddress((void**)&p_kc,  g_kc);
    cudaGetSymbolAddress((void**)&p_v,   g_v);
    cudaGetSymbolAddress((void**)&p_qsT, g_qsT);
    cudaGetSymbolAddress((void**)&p_ksT, g_ksT);
    cudaGetSymbolAddress((void**)&p_qcT, g_qcT);
    cudaGetSymbolAddress((void**)&p_kcT, g_kcT);
    cudaGetSymbolAddress((void**)&p_o,   g_o);

    static int init_done = 0;
    if (!init_done) {
        cudaFuncSetAttribute(sca_kernel, cudaFuncAttributeMaxDynamicSharedMemorySize, SCA_SM_FLOATS*4);
        cudaFuncSetAttribute(ssa_kernel, cudaFuncAttributeMaxDynamicSharedMemorySize, SSA_SM_FLOATS*4);
        init_done = 1;
    }

    // 5 in-projections in one launch
    GemmBatch gb;
    gb.x[0] = qsem;  gb.c[0] = p_qs; gb.woff[0] = 0;
    gb.x[1] = ksem;  gb.c[1] = p_ks; gb.woff[1] = 512;
    gb.x[2] = query; gb.c[2] = p_qc; gb.woff[2] = 0;
    gb.x[3] = key;   gb.c[3] = p_kc; gb.woff[3] = 512;
    gb.x[4] = value; gb.c[4] = p_v;  gb.woff[4] = 1024;
    gemm_bias5<<<dim3(EMB/64, NROWS/128, 5), 256>>>(gb, Wi, bi);

    // 4 transposes in one launch
    TransBatch tb;
    tb.src[0] = p_qs; tb.dst[0] = p_qsT; tb.scale[0] = 0.125f;
    tb.src[1] = p_ks; tb.dst[1] = p_ksT; tb.scale[1] = 1.0f;
    tb.src[2] = p_qc; tb.dst[2] = p_qcT; tb.scale[2] = 0.125f;
    tb.src[3] = p_kc; tb.dst[3] = p_kcT; tb.scale[3] = 1.0f;
    transpose_head4<<<dim3(SEQ/32, HDIM/32, 4*NBH), 256>>>(tb);

    ssa_kernel<<<dim3(SEQ/128, NBH), 256, SSA_SM_FLOATS*4>>>(smap);
    sca_kernel<<<dim3(SEQ/64, NBH), 256, SCA_SM_FLOATS*4>>>(smap, p_o);

    gemm_bias<<<dim3(EMB/64, NROWS/128), 256>>>(p_o, Wo, bo, out, T1C + T2C);
}

// round 5
// speedup vs baseline: 1.8143x; 1.0118x over previous
#include <cuda_runtime.h>
#include <math.h>
#include <stdint.h>

#define SEQ   1024
#define BSZ   8
#define EMB   512
#define NHEAD 8
#define HDIM  64
#define NROWS (SEQ*BSZ)      // 8192
#define NBH   (BSZ*NHEAD)    // 64
#define FLTMAX 3.402823466e38f
#define T1C 0.6f
#define T2C 0.4f

typedef unsigned long long ull;

// ---------------- packed f32x2 helpers ------------------------------------------
__device__ __forceinline__ ull pack2(float x, float y) {
    ull r; asm("mov.b64 %0, {%1, %2};" : "=l"(r) : "f"(x), "f"(y)); return r;
}
__device__ __forceinline__ ull dup2(float x) { return pack2(x, x); }
__device__ __forceinline__ void fma2(ull& d, ull a, ull b) {
    asm("fma.rn.f32x2 %0, %1, %2, %0;" : "+l"(d) : "l"(a), "l"(b));
}
__device__ __forceinline__ void mul2(ull& d, ull a) {
    asm("mul.rn.f32x2 %0, %0, %1;" : "+l"(d) : "l"(a));
}
__device__ __forceinline__ void unpack2(ull v, float& lo, float& hi) {
    asm("mov.b64 {%0, %1}, %2;" : "=f"(lo), "=f"(hi) : "l"(v));
}
// ---------------- cp.async helpers ----------------------------------------------
__device__ __forceinline__ uint32_t sptr(const void* p) {
    return (uint32_t)__cvta_generic_to_shared(p);
}
__device__ __forceinline__ void cpa16(uint32_t s, const void* g) {
    asm volatile("cp.async.cg.shared.global [%0], [%1], 16;" :: "r"(s), "l"(g));
}
__device__ __forceinline__ void cpa_commit() { asm volatile("cp.async.commit_group;"); }
__device__ __forceinline__ void cpa_wait0()  { asm volatile("cp.async.wait_group 0;" ::: "memory"); }

// ---------------- scratch (device globals; no allocation allowed) ---------------
__device__ float g_qs [NROWS*EMB];
__device__ float g_ks [NROWS*EMB];
__device__ float g_qc [NROWS*EMB];
__device__ float g_kc [NROWS*EMB];
__device__ float g_v  [NROWS*EMB];
__device__ float g_qsT[NBH*HDIM*SEQ];   // [bh][d][t], q pre-scaled by 1/8
__device__ float g_ksT[NBH*HDIM*SEQ];
__device__ float g_qcT[NBH*HDIM*SEQ];
__device__ float g_kcT[NBH*HDIM*SEQ];
__device__ float g_o  [NROWS*EMB];
__device__ int   g_idx[NBH*SEQ];

struct GemmBatch {
    const float* x[5];
    float*       c[5];
    int          woff[5];
};
struct TransBatch {
    const float* src[4];
    float*       dst[4];
    float        scale[4];
};

// -------- fp32 GEMM (FFMA2): 128x128 tile, 256 thr, 8Mx8N/thread ----------------
__device__ __forceinline__ void gemm_body(const float* __restrict__ X,
                                          const float* __restrict__ W,
                                          const float* __restrict__ bias,
                                          float* __restrict__ C, float bscale) {
    __shared__ float As[16][132];
    __shared__ float Bs[16][132];
    const int bm = blockIdx.y << 7;
    const int bn = blockIdx.x << 7;
    const int tid = threadIdx.x;
    const int mg = tid >> 4;        // 16 groups * 8 rows
    const int ng = tid & 15;        // 16 groups * 8 cols
    const int ar = tid >> 1;        // staging row 0..127
    const int af = (tid & 1) << 3;  // staging k offset 0/8

    ull acc2[4][8];
#pragma unroll
    for (int p = 0; p < 4; p++)
#pragma unroll
        for (int j = 0; j < 8; j++) acc2[p][j] = 0ull;

    const float* xp = X + (size_t)(bm + ar) * EMB + af;
    const float* wp = W + (size_t)(bn + ar) * EMB + af;

    float4 xa0 = *(const float4*)(xp);
    float4 xa1 = *(const float4*)(xp + 4);
    float4 wb0 = *(const float4*)(wp);
    float4 wb1 = *(const float4*)(wp + 4);

    for (int k0 = 0; k0 < EMB; k0 += 16) {
        __syncthreads();
        As[af+0][ar] = xa0.x; As[af+1][ar] = xa0.y; As[af+2][ar] = xa0.z; As[af+3][ar] = xa0.w;
        As[af+4][ar] = xa1.x; As[af+5][ar] = xa1.y; As[af+6][ar] = xa1.z; As[af+7][ar] = xa1.w;
        Bs[af+0][ar] = wb0.x; Bs[af+1][ar] = wb0.y; Bs[af+2][ar] = wb0.z; Bs[af+3][ar] = wb0.w;
        Bs[af+4][ar] = wb1.x; Bs[af+5][ar] = wb1.y; Bs[af+6][ar] = wb1.z; Bs[af+7][ar] = wb1.w;
        __syncthreads();
        if (k0 + 16 < EMB) {
            xa0 = *(const float4*)(xp + k0 + 16);
            xa1 = *(const float4*)(xp + k0 + 20);
            wb0 = *(const float4*)(wp + k0 + 16);
            wb1 = *(const float4*)(wp + k0 + 20);
        }
#pragma unroll
        for (int k = 0; k < 16; k++) {
            ulonglong2 a01 = *(const ulonglong2*)&As[k][mg << 3];
            ulonglong2 a23 = *(const ulonglong2*)&As[k][(mg << 3) + 4];
            float4 b0 = *(const float4*)&Bs[k][ng << 3];
            float4 b1 = *(const float4*)&Bs[k][(ng << 3) + 4];
            ull bd[8];
            bd[0] = dup2(b0.x); bd[1] = dup2(b0.y); bd[2] = dup2(b0.z); bd[3] = dup2(b0.w);
            bd[4] = dup2(b1.x); bd[5] = dup2(b1.y); bd[6] = dup2(b1.z); bd[7] = dup2(b1.w);
#pragma unroll
            for (int j = 0; j < 8; j++) {
                fma2(acc2[0][j], a01.x, bd[j]);
                fma2(acc2[1][j], a01.y, bd[j]);
                fma2(acc2[2][j], a23.x, bd[j]);
                fma2(acc2[3][j], a23.y, bd[j]);
            }
        }
    }

    float bb[8];
#pragma unroll
    for (int j = 0; j < 8; j++) bb[j] = bias[bn + (ng<<3) + j] * bscale;
#pragma unroll
    for (int p = 0; p < 4; p++) {
        float lo[8], hi[8];
#pragma unroll
        for (int j = 0; j < 8; j++) unpack2(acc2[p][j], lo[j], hi[j]);
        int r0 = bm + (mg << 3) + (p << 1);
        float* c0 = &C[(size_t)r0 * EMB + bn + (ng<<3)];
        float* c1 = &C[(size_t)(r0+1) * EMB + bn + (ng<<3)];
        *(float4*)(c0)   = make_float4(lo[0]+bb[0], lo[1]+bb[1], lo[2]+bb[2], lo[3]+bb[3]);
        *(float4*)(c0+4) = make_float4(lo[4]+bb[4], lo[5]+bb[5], lo[6]+bb[6], lo[7]+bb[7]);
        *(float4*)(c1)   = make_float4(hi[0]+bb[0], hi[1]+bb[1], hi[2]+bb[2], hi[3]+bb[3]);
        *(float4*)(c1+4) = make_float4(hi[4]+bb[4], hi[5]+bb[5], hi[6]+bb[6], hi[7]+bb[7]);
    }
}

__global__ __launch_bounds__(256, 2)
void gemm_bias5(GemmBatch gb, const float* __restrict__ W, const float* __restrict__ bias) {
    const int z = blockIdx.z;
    gemm_body(gb.x[z], W + (size_t)gb.woff[z] * EMB, bias + gb.woff[z], gb.c[z], 1.0f);
}

__global__ __launch_bounds__(256, 2)
void gemm_bias(const float* __restrict__ X, const float* __restrict__ W,
               const float* __restrict__ bias, float* __restrict__ C, float bscale) {
    gemm_body(X, W, bias, C, bscale);
}

// ------- head transpose x4 ------------------------------------------------------
__global__ __launch_bounds__(256)
void transpose_head4(TransBatch tb) {
    __shared__ float tile[32][33];
    const int z = blockIdx.z;
    const int var = z >> 6, bh = z & 63;
    const int b = bh >> 3, h = bh & 7;
    const float* in  = tb.src[var];
    float* out = tb.dst[var];
    const float scale = tb.scale[var];
    const int t0 = blockIdx.x << 5;
    const int d0 = blockIdx.y << 5;
    const int tx = threadIdx.x & 31, ty = threadIdx.x >> 5;
#pragma unroll
    for (int i = 0; i < 32; i += 8)
        tile[ty + i][tx] = in[(size_t)(t0 + ty + i) * (BSZ*EMB) + b * EMB + h * HDIM + d0 + tx] * scale;
    __syncthreads();
#pragma unroll
    for (int i = 0; i < 32; i += 8)
        out[(size_t)(bh * HDIM + d0 + ty + i) * SEQ + t0 + tx] = tile[tx][ty + i];
}

// ---------------- SSA kernel: scores + running argmax ---------------------------
// 128q x 64s tiles. smem: qT[64][128], kT[2][64][64]. cp.async double-buffered k.
#define SSA_SM_FLOATS (64*128 + 2*64*64)

__device__ __forceinline__ void ssa_issue(int s0, float* kbuf, int tid, int bh) {
    for (int i = tid; i < 1024; i += 256) {
        int d = i >> 4, g = (i & 15) << 2;
        cpa16(sptr(kbuf + d*64 + g), &g_kcT[(size_t)(bh*HDIM + d)*SEQ + s0 + g]);
    }
    cpa_commit();
}

__global__ __launch_bounds__(256, 2)
void ssa_kernel(const float* __restrict__ sem_map) {
    extern __shared__ float sm[];
    float* qTs = sm;            // [d][128]
    float* kT  = sm + 64*128;   // 2 buffers of [d][64]

    const int bh = blockIdx.y;
    const int q0 = blockIdx.x << 7;
    const int tid = threadIdx.x;
    const int rg = tid >> 4;    // 16 x 8q
    const int cg = tid & 15;    // 16 x 4s

    for (int i = tid; i < 2048; i += 256) {
        int d = i >> 5, g = (i & 31) << 2;
        *(float4*)&qTs[d*128 + g] = *(const float4*)&g_qcT[(size_t)(bh*HDIM + d)*SEQ + q0 + g];
    }

    float bsc[8];
    int   bix[8];
#pragma unroll
    for (int i = 0; i < 8; i++) { bsc[i] = -FLTMAX; bix[i] = 0; }

    const float* qb = &qTs[rg << 3];
    ssa_issue(0, kT, tid, bh);

    for (int it = 0; it < 16; it++) {
        const int s0 = it << 6;
        cpa_wait0();
        __syncthreads();
        if (it + 1 < 16) ssa_issue(s0 + 64, kT + ((it + 1) & 1) * 4096, tid, bh);

        const float* kb = kT + (it & 1) * 4096 + (cg << 2);

        ull sc2[4][4];
#pragma unroll
        for (int i = 0; i < 4; i++)
#pragma unroll
            for (int j = 0; j < 4; j++) sc2[i][j] = 0ull;

#pragma unroll 4
        for (int d = 0; d < 64; d++) {
            ulonglong2 q01 = *(const ulonglong2*)(qb + d*128);
            ulonglong2 q23 = *(const ulonglong2*)(qb + d*128 + 4);
            float4 kv = *(const float4*)(kb + d*64);
            ull k0 = dup2(kv.x), k1 = dup2(kv.y), k2 = dup2(kv.z), k3 = dup2(kv.w);
            fma2(sc2[0][0], q01.x, k0); fma2(sc2[0][1], q01.x, k1);
            fma2(sc2[0][2], q01.x, k2); fma2(sc2[0][3], q01.x, k3);
            fma2(sc2[1][0], q01.y, k0); fma2(sc2[1][1], q01.y, k1);
            fma2(sc2[1][2], q01.y, k2); fma2(sc2[1][3], q01.y, k3);
            fma2(sc2[2][0], q23.x, k0); fma2(sc2[2][1], q23.x, k1);
            fma2(sc2[2][2], q23.x, k2); fma2(sc2[2][3], q23.x, k3);
            fma2(sc2[3][0], q23.y, k0); fma2(sc2[3][1], q23.y, k1);
            fma2(sc2[3][2], q23.y, k2); fma2(sc2[3][3], q23.y, k3);
        }

#pragma unroll
        for (int qp = 0; qp < 4; qp++) {
            float s0v[4], s1v[4];
#pragma unroll
            for (int j = 0; j < 4; j++) unpack2(sc2[qp][j], s0v[j], s1v[j]);
            int i0 = (qp << 1), i1 = i0 + 1;
            float4 mk0 = *(const float4*)&sem_map[(size_t)(q0 + (rg<<3) + i0)*SEQ + s0 + (cg<<2)];
            float4 mk1 = *(const float4*)&sem_map[(size_t)(q0 + (rg<<3) + i1)*SEQ + s0 + (cg<<2)];
            float ma[4] = {mk0.x, mk0.y, mk0.z, mk0.w};
            float mb[4] = {mk1.x, mk1.y, mk1.z, mk1.w};
#pragma unroll
            for (int j = 0; j < 4; j++) {
                float va = (ma[j] < 0.5f) ? -FLTMAX : s0v[j];
                float vb = (mb[j] < 0.5f) ? -FLTMAX : s1v[j];
                if (va > bsc[i0]) { bsc[i0] = va; bix[i0] = s0 + (cg<<2) + j; }
                if (vb > bsc[i1]) { bsc[i1] = vb; bix[i1] = s0 + (cg<<2) + j; }
            }
        }
    }

#pragma unroll
    for (int i = 0; i < 8; i++) {
        float bs = bsc[i]; int bi = bix[i];
#pragma unroll
        for (int off = 1; off < 16; off <<= 1) {
            float os = __shfl_xor_sync(0xffffffffu, bs, off, 16);
            int   oi = __shfl_xor_sync(0xffffffffu, bi, off, 16);
            if (os > bs || (os == bs && oi < bi)) { bs = os; bi = oi; }
        }
        if (cg == 0) g_idx[bh*SEQ + q0 + (rg<<3) + i] = bi;
    }
}

// ---------------- SCA kernel: softmax attention + combine -----------------------
// 64q x 64s tiles. cp.async double-buffered k,v. wt stored [s][q] for vector PV.
#define SCA_QT   0
#define SCA_KT   4096                 // 2 x 4096
#define SCA_VT   12288                // 2 x 4352 ([s][68])
#define SCA_WT   20992                // [s][68] -> w[s][q]
#define SCA_FAC  25344
#define SCA_L    25408
#define SCA_SM_FLOATS 25472

__device__ __forceinline__ void sca_issue(int s0, float* kbuf, float* vbuf,
                                          int tid, int bh, int b, int h) {
    for (int i = tid; i < 1024; i += 256) {
        int d = i >> 4, g = (i & 15) << 2;
        cpa16(sptr(kbuf + d*64 + g), &g_ksT[(size_t)(bh*HDIM + d)*SEQ + s0 + g]);
    }
    for (int i = tid; i < 1024; i += 256) {
        int r = i >> 4, d4 = (i & 15) << 2;
        cpa16(sptr(vbuf + r*68 + d4), &g_v[(size_t)((s0 + r)*BSZ + b)*EMB + h*HDIM + d4]);
    }
    cpa_commit();
}

__global__ __launch_bounds__(256, 2)
void sca_kernel(const float* __restrict__ sem_map, float* __restrict__ Ocomb) {
    extern __shared__ float sm[];
    float* qTs  = sm + SCA_QT;
    float* kT   = sm + SCA_KT;
    float* vT   = sm + SCA_VT;
    float* wts  = sm + SCA_WT;    // [s][68] storing w[s][q]
    float* sfac = sm + SCA_FAC;
    float* sl   = sm + SCA_L;

    const int bh = blockIdx.y, b = bh >> 3, h = bh & 7;
    const int q0 = blockIdx.x << 6;
    const int tid = threadIdx.x;
    const int rg = tid >> 4;     // 16 x 4q
    const int cgs = tid & 15;    // 16 x 4s

    for (int i = tid; i < 1024; i += 256) {
        int d = i >> 4, g = (i & 15) << 2;
        *(float4*)&qTs[d*64 + g] = *(const float4*)&g_qsT[(size_t)(bh*HDIM + d)*SEQ + q0 + g];
    }

    float mrun[4], lrun[4];
#pragma unroll
    for (int i = 0; i < 4; i++) { mrun[i] = -FLTMAX; lrun[i] = 0.f; }

    const int qg = tid >> 4;
    const int dgp = tid & 15;
    ull acc2[4][2];
#pragma unroll
    for (int i = 0; i < 4; i++) { acc2[i][0] = 0ull; acc2[i][1] = 0ull; }

    const float* qb = &qTs[rg << 2];
    sca_issue(0, kT, vT, tid, bh, b, h);

    for (int it = 0; it < 16; it++) {
        const int s0 = it << 6;
        cpa_wait0();
        __syncthreads();
        if (it + 1 < 16)
            sca_issue(s0 + 64, kT + ((it+1) & 1)*4096, vT + ((it+1) & 1)*4352, tid, bh, b, h);

        const float* kb = kT + (it & 1)*4096 + (cgs << 2);
        const float* vts = vT + (it & 1)*4352;

        // scores 4q x 4s, acc pairs along s
        ull sc2[4][2];
#pragma unroll
        for (int i = 0; i < 4; i++) { sc2[i][0] = 0ull; sc2[i][1] = 0ull; }
#pragma unroll 8
        for (int d = 0; d < 64; d++) {
            float4 qa = *(const float4*)(qb + d*64);
            ulonglong2 kk = *(const ulonglong2*)(kb + d*64);
            ull q0d = dup2(qa.x), q1d = dup2(qa.y), q2d = dup2(qa.z), q3d = dup2(qa.w);
            fma2(sc2[0][0], q0d, kk.x); fma2(sc2[0][1], q0d, kk.y);
            fma2(sc2[1][0], q1d, kk.x); fma2(sc2[1][1], q1d, kk.y);
            fma2(sc2[2][0], q2d, kk.x); fma2(sc2[2][1], q2d, kk.y);
            fma2(sc2[3][0], q3d, kk.x); fma2(sc2[3][1], q3d, kk.y);
        }

        float sc[4][4];
#pragma unroll
        for (int i = 0; i < 4; i++) {
            unpack2(sc2[i][0], sc[i][0], sc[i][1]);
            unpack2(sc2[i][1], sc[i][2], sc[i][3]);
        }
#pragma unroll
        for (int i = 0; i < 4; i++) {
            float4 mk = *(const float4*)&sem_map[(size_t)(q0 + (rg<<2) + i)*SEQ + s0 + (cgs<<2)];
            if (mk.x < 0.5f) sc[i][0] = -FLTMAX;
            if (mk.y < 0.5f) sc[i][1] = -FLTMAX;
            if (mk.z < 0.5f) sc[i][2] = -FLTMAX;
            if (mk.w < 0.5f) sc[i][3] = -FLTMAX;
        }
        // online softmax; weights stored transposed wt[s][q]
        float w[4][4];
#pragma unroll
        for (int i = 0; i < 4; i++) {
            float tm = fmaxf(fmaxf(sc[i][0], sc[i][1]), fmaxf(sc[i][2], sc[i][3]));
#pragma unroll
            for (int off = 1; off < 16; off <<= 1)
                tm = fmaxf(tm, __shfl_xor_sync(0xffffffffu, tm, off, 16));
            float mnew = fmaxf(mrun[i], tm);
            float fac  = __expf(mrun[i] - mnew);
            w[i][0] = __expf(sc[i][0] - mnew);
            w[i][1] = __expf(sc[i][1] - mnew);
            w[i][2] = __expf(sc[i][2] - mnew);
            w[i][3] = __expf(sc[i][3] - mnew);
            float sum = (w[i][0] + w[i][1]) + (w[i][2] + w[i][3]);
#pragma unroll
            for (int off = 1; off < 16; off <<= 1)
                sum += __shfl_xor_sync(0xffffffffu, sum, off, 16);
            lrun[i] = lrun[i] * fac + sum;
            mrun[i] = mnew;
            if (cgs == 0) sfac[(rg<<2) + i] = fac;
        }
#pragma unroll
        for (int j = 0; j < 4; j++)
            *(float4*)&wts[((cgs<<2) + j)*68 + (rg<<2)] =
                make_float4(w[0][j], w[1][j], w[2][j], w[3][j]);
        __syncthreads();

        // PV: 4q x 4d per thread; w loaded as broadcast float4 per s
        {
            ull f0 = dup2(sfac[(qg<<2) + 0]);
            ull f1 = dup2(sfac[(qg<<2) + 1]);
            ull f2 = dup2(sfac[(qg<<2) + 2]);
            ull f3 = dup2(sfac[(qg<<2) + 3]);
            mul2(acc2[0][0], f0); mul2(acc2[0][1], f0);
            mul2(acc2[1][0], f1); mul2(acc2[1][1], f1);
            mul2(acc2[2][0], f2); mul2(acc2[2][1], f2);
            mul2(acc2[3][0], f3); mul2(acc2[3][1], f3);
#pragma unroll 8
            for (int s = 0; s < 64; s++) {
                float4 w4 = *(const float4*)&wts[s*68 + (qg<<2)];
                ulonglong2 vv = *(const ulonglong2*)&vts[s*68 + (dgp<<2)];
                ull w0 = dup2(w4.x), w1 = dup2(w4.y), w2 = dup2(w4.z), w3 = dup2(w4.w);
                fma2(acc2[0][0], w0, vv.x); fma2(acc2[0][1], w0, vv.y);
                fma2(acc2[1][0], w1, vv.x); fma2(acc2[1][1], w1, vv.y);
                fma2(acc2[2][0], w2, vv.x); fma2(acc2[2][1], w2, vv.y);
                fma2(acc2[3][0], w3, vv.x); fma2(acc2[3][1], w3, vv.y);
            }
        }
    }

    if (cgs == 0) {
#pragma unroll
        for (int i = 0; i < 4; i++) sl[(rg<<2) + i] = lrun[i];
    }
    __syncthreads();

#pragma unroll
    for (int i = 0; i < 4; i++) {
        int qr = (qg<<2) + i;
        float rl = 1.0f / sl[qr];
        int   bi = g_idx[bh*SEQ + q0 + qr];
        float4 va = *(const float4*)&g_v[(size_t)(bi*BSZ + b)*EMB + h*HDIM + (dgp<<2)];
        float a0, a1, a2, a3;
        unpack2(acc2[i][0], a0, a1);
        unpack2(acc2[i][1], a2, a3);
        float4 o;
        o.x = T1C*a0*rl + T2C*va.x;
        o.y = T1C*a1*rl + T2C*va.y;
        o.z = T1C*a2*rl + T2C*va.z;
        o.w = T1C*a3*rl + T2C*va.w;
        *(float4*)&Ocomb[(size_t)((q0 + qr)*BSZ + b)*EMB + h*HDIM + (dgp<<2)] = o;
    }
}

// -------------------------------------------------------------------------------
extern "C" void kernel_launch(void* const* d_in, const int* in_sizes, int n_in,
                              void* d_out, int out_size) {
    const float* query = (const float*)d_in[0];
    const float* key   = (const float*)d_in[1];
    const float* value = (const float*)d_in[2];
    const float* qsem  = (const float*)d_in[3];
    const float* ksem  = (const float*)d_in[4];
    const float* smap  = (const float*)d_in[5];
    const float* Wi    = (const float*)d_in[6];
    const float* bi    = (const float*)d_in[7];
    const float* Wo    = (const float*)d_in[8];
    const float* bo    = (const float*)d_in[9];
    float* out = (float*)d_out;

    float *p_qs, *p_ks, *p_qc, *p_kc, *p_v, *p_qsT, *p_ksT, *p_qcT, *p_kcT, *p_o;
    cudaGetSymbolAddress((void**)&p_qs,  g_qs);
    cudaGetSymbolAddress((void**)&p_ks,  g_ks);
    cudaGetSymbolAddress((void**)&p_qc,  g_qc);
    cudaGetSymbolAddress((void**)&p_kc,  g_kc);
    cudaGetSymbolAddress((void**)&p_v,   g_v);
    cudaGetSymbolAddress((void**)&p_qsT, g_qsT);
    cudaGetSymbolAddress((void**)&p_ksT, g_ksT);
    cudaGetSymbolAddress((void**)&p_qcT, g_qcT);
    cudaGetSymbolAddress((void**)&p_kcT, g_kcT);
    cudaGetSymbolAddress((void**)&p_o,   g_o);

    static int init_done = 0;
    if (!init_done) {
        cudaFuncSetAttribute(sca_kernel, cudaFuncAttributeMaxDynamicSharedMemorySize, SCA_SM_FLOATS*4);
        cudaFuncSetAttribute(ssa_kernel, cudaFuncAttributeMaxDynamicSharedMemorySize, SSA_SM_FLOATS*4);
        init_done = 1;
    }

    GemmBatch gb;
    gb.x[0] = qsem;  gb.c[0] = p_qs; gb.woff[0] = 0;
    gb.x[1] = ksem;  gb.c[1] = p_ks; gb.woff[1] = 512;
    gb.x[2] = query; gb.c[2] = p_qc; gb.woff[2] = 0;
    gb.x[3] = key;   gb.c[3] = p_kc; gb.woff[3] = 512;
    gb.x[4] = value; gb.c[4] = p_v;  gb.woff[4] = 1024;
    gemm_bias5<<<dim3(EMB/128, NROWS/128, 5), 256>>>(gb, Wi, bi);

    TransBatch tb;
    tb.src[0] = p_qs; tb.dst[0] = p_qsT; tb.scale[0] = 0.125f;
    tb.src[1] = p_ks; tb.dst[1] = p_ksT; tb.scale[1] = 1.0f;
    tb.src[2] = p_qc; tb.dst[2] = p_qcT; tb.scale[2] = 0.125f;
    tb.src[3] = p_kc; tb.dst[3] = p_kcT; tb.scale[3] = 1.0f;
    transpose_head4<<<dim3(SEQ/32, HDIM/32, 4*NBH), 256>>>(tb);

    ssa_kernel<<<dim3(SEQ/128, NBH), 256, SSA_SM_FLOATS*4>>>(smap);
    sca_kernel<<<dim3(SEQ/64, NBH), 256, SCA_SM_FLOATS*4>>>(smap, p_o);

    gemm_bias<<<dim3(EMB/128, NROWS/128), 256>>>(p_o, Wo, bo, out, T1C + T2C);
}